// round 1
// baseline (speedup 1.0000x reference)
#include <cuda_runtime.h>
#include <cuda_bf16.h>

// ---------------- problem constants ----------------
#define BATCH   4
#define LSEQ    4096
#define NTOK    (BATCH*LSEQ)       // 16384
#define DM      512
#define DI      512
#define DS      8
#define DTRANK  32
#define DBCW    48                 // DT_RANK + 2*D_STATE

// chunked scan config
#define NCH     32
#define TCH     (LSEQ/NCH)         // 128
#define NCHAN   (BATCH*DI)         // 2048
#define CHTOT   (NCHAN*NCH)        // 65536

// ---------------- scratch (device globals; no runtime alloc) ----------------
__device__ float g_hln [NTOK*DM];
__device__ float g_xz  [NTOK*2*DI];
__device__ float g_xc0 [NTOK*DI];
__device__ float g_xc1 [NTOK*DI];
__device__ float g_dbc0[NTOK*DBCW];
__device__ float g_dbc1[NTOK*DBCW];
__device__ float g_de0 [NTOK*DI];
__device__ float g_de1 [NTOK*DI];
__device__ float g_y0  [NTOK*DI];
__device__ float g_y1  [NTOK*DI];
__device__ float g_yn  [NTOK*DI];
__device__ float g_P0  [DS*CHTOT];
__device__ float g_Q0  [DS*CHTOT];
__device__ float g_H00 [DS*CHTOT];
__device__ float g_P1  [DS*CHTOT];
__device__ float g_Q1  [DS*CHTOT];
__device__ float g_H01 [DS*CHTOT];

// ---------------- LayerNorm: one warp per token (512 elems) ----------------
__global__ void k_layernorm(const float* __restrict__ x,
                            const float* __restrict__ w,
                            const float* __restrict__ b,
                            float* __restrict__ out)
{
    int tok  = blockIdx.x * 8 + (threadIdx.x >> 5);
    int lane = threadIdx.x & 31;
    const float* row = x + (size_t)tok * DM;

    float4 v[4];
    float s = 0.f, s2 = 0.f;
#pragma unroll
    for (int i = 0; i < 4; i++) {
        v[i] = *(const float4*)(row + i * 128 + lane * 4);
        s  += v[i].x + v[i].y + v[i].z + v[i].w;
        s2 += v[i].x*v[i].x + v[i].y*v[i].y + v[i].z*v[i].z + v[i].w*v[i].w;
    }
#pragma unroll
    for (int o = 16; o; o >>= 1) {
        s  += __shfl_xor_sync(0xffffffffu, s,  o);
        s2 += __shfl_xor_sync(0xffffffffu, s2, o);
    }
    float mu   = s * (1.f / DM);
    float var  = s2 * (1.f / DM) - mu * mu;
    float rinv = rsqrtf(var + 1e-5f);

    float* orow = out + (size_t)tok * DM;
#pragma unroll
    for (int i = 0; i < 4; i++) {
        int d = i * 128 + lane * 4;
        float4 w4 = *(const float4*)(w + d);
        float4 b4 = *(const float4*)(b + d);
        float4 o4;
        o4.x = (v[i].x - mu) * rinv * w4.x + b4.x;
        o4.y = (v[i].y - mu) * rinv * w4.y + b4.y;
        o4.z = (v[i].z - mu) * rinv * w4.z + b4.z;
        o4.w = (v[i].w - mu) * rinv * w4.w + b4.w;
        *(float4*)(orow + d) = o4;
    }
}

// ---------------- SGEMM: C[M,N] = A[M,K](lda) * W[N,K]^T, fp32 ----------------
#define BM 64
#define BN 64
#define BKK 16

enum { EP_NONE = 0, EP_SOFTPLUS = 1, EP_RESID = 2 };

template<int EPI>
__global__ __launch_bounds__(256)
void k_gemm(const float* __restrict__ A, int lda,
            const float* __restrict__ W,
            float* __restrict__ C,
            int M, int N, int K,
            const float* __restrict__ bias,
            const float* __restrict__ resid)
{
    __shared__ __align__(16) float As[BKK][BM + 4];
    __shared__ __align__(16) float Ws[BKK][BN + 4];

    const int bm = blockIdx.y * BM;
    const int bn = blockIdx.x * BN;
    const int tid = threadIdx.x;
    const int tx = tid & 15;      // N dim
    const int ty = tid >> 4;      // M dim
    const int lr = tid >> 2;      // load row 0..63
    const int lq = tid & 3;       // load quad 0..3

    float acc[4][4];
#pragma unroll
    for (int i = 0; i < 4; i++)
#pragma unroll
        for (int j = 0; j < 4; j++) acc[i][j] = 0.f;

    const bool wok = (bn + lr) < N;
    const float* Ap = A + (size_t)(bm + lr) * lda + lq * 4;
    const float* Wp = W + (size_t)(wok ? (bn + lr) : 0) * K + lq * 4;

    for (int k0 = 0; k0 < K; k0 += BKK) {
        float4 av = *(const float4*)(Ap + k0);
        float4 wv = wok ? *(const float4*)(Wp + k0) : make_float4(0.f, 0.f, 0.f, 0.f);
        __syncthreads();
        As[lq*4+0][lr] = av.x; As[lq*4+1][lr] = av.y;
        As[lq*4+2][lr] = av.z; As[lq*4+3][lr] = av.w;
        Ws[lq*4+0][lr] = wv.x; Ws[lq*4+1][lr] = wv.y;
        Ws[lq*4+2][lr] = wv.z; Ws[lq*4+3][lr] = wv.w;
        __syncthreads();
#pragma unroll
        for (int kk = 0; kk < BKK; kk++) {
            float4 ra = *(const float4*)(&As[kk][ty * 4]);
            float4 rw = *(const float4*)(&Ws[kk][tx * 4]);
            float a4[4] = { ra.x, ra.y, ra.z, ra.w };
            float w4[4] = { rw.x, rw.y, rw.z, rw.w };
#pragma unroll
            for (int i = 0; i < 4; i++)
#pragma unroll
                for (int j = 0; j < 4; j++)
                    acc[i][j] = fmaf(a4[i], w4[j], acc[i][j]);
        }
    }

#pragma unroll
    for (int i = 0; i < 4; i++) {
        int m = bm + ty * 4 + i;
#pragma unroll
        for (int j = 0; j < 4; j++) {
            int n = bn + tx * 4 + j;
            if (n < N) {
                float v = acc[i][j];
                if (EPI == EP_SOFTPLUS) {
                    v += bias[n];
                    v = (v > 20.f) ? v : log1pf(__expf(v));
                }
                if (EPI == EP_RESID) v += resid[(size_t)m * N + n];
                C[(size_t)m * N + n] = v;
            }
        }
    }
}

// ---------------- causal depthwise conv (k=2) + SiLU, fwd + reversed-bwd ------
__global__ void k_conv(const float* __restrict__ xz,
                       const float* __restrict__ cw,  const float* __restrict__ cb,
                       const float* __restrict__ cwb, const float* __restrict__ cbb,
                       float* __restrict__ xcf, float* __restrict__ xcb)
{
    int flat = blockIdx.x * blockDim.x + threadIdx.x;   // NTOK*DI threads
    int d   = flat & (DI - 1);
    int tok = flat >> 9;
    int b   = tok >> 12;          // tok / LSEQ
    int s   = tok & (LSEQ - 1);

    // forward: xc[s] = w0*x[s-1] + w1*x[s] + b
    float xcur = xz[(size_t)tok * (2 * DI) + d];
    float xprv = (s > 0) ? xz[(size_t)(tok - 1) * (2 * DI) + d] : 0.f;
    float vf = fmaf(cw[d * 2 + 0], xprv, fmaf(cw[d * 2 + 1], xcur, cb[d]));
    xcf[flat] = vf / (1.f + __expf(-vf));

    // backward (reversed-time space): xrev[s]=x[L-1-s]
    int t1 = b * LSEQ + (LSEQ - 1 - s);
    float xcb_cur = xz[(size_t)t1 * (2 * DI) + d];
    float xcb_prv = (s > 0) ? xz[(size_t)(t1 + 1) * (2 * DI) + d] : 0.f;
    float vb = fmaf(cwb[d * 2 + 0], xcb_prv, fmaf(cwb[d * 2 + 1], xcb_cur, cbb[d]));
    xcb[flat] = vb / (1.f + __expf(-vb));
}

// ---------------- scan pass 1: per-chunk (P = prod a, q = h with h0=0) -------
__global__ void k_scan1(const float* __restrict__ delta, const float* __restrict__ u,
                        const float* __restrict__ dbc,   const float* __restrict__ A_log,
                        float* __restrict__ Ps, float* __restrict__ Qs)
{
    int flat = blockIdx.x * blockDim.x + threadIdx.x;   // CHTOT threads
    int d     = flat & (DI - 1);
    int b     = (flat >> 9) & (BATCH - 1);
    int chunk = flat >> 11;

    float Av[DS];
    float4 a0 = *(const float4*)(A_log + d * DS);
    float4 a1 = *(const float4*)(A_log + d * DS + 4);
    Av[0] = -__expf(a0.x); Av[1] = -__expf(a0.y); Av[2] = -__expf(a0.z); Av[3] = -__expf(a0.w);
    Av[4] = -__expf(a1.x); Av[5] = -__expf(a1.y); Av[6] = -__expf(a1.z); Av[7] = -__expf(a1.w);

    float h[DS], P[DS];
#pragma unroll
    for (int n = 0; n < DS; n++) { h[n] = 0.f; P[n] = 1.f; }

    int tok = b * LSEQ + chunk * TCH;
    for (int t = 0; t < TCH; t++, tok++) {
        float dl = delta[(size_t)tok * DI + d];
        float uu = u[(size_t)tok * DI + d];
        float du = dl * uu;
        const float4* Bp = (const float4*)(dbc + (size_t)tok * DBCW + DTRANK);
        float4 B0 = Bp[0], B1 = Bp[1];
        float Bv[DS] = { B0.x, B0.y, B0.z, B0.w, B1.x, B1.y, B1.z, B1.w };
#pragma unroll
        for (int n = 0; n < DS; n++) {
            float a = __expf(dl * Av[n]);
            P[n] *= a;
            h[n] = fmaf(a, h[n], du * Bv[n]);
        }
    }
#pragma unroll
    for (int n = 0; n < DS; n++) {
        Ps[n * CHTOT + flat] = P[n];
        Qs[n * CHTOT + flat] = h[n];
    }
}

// ---------------- scan combine: serial stitch across chunks ------------------
__global__ void k_scanc(const float* __restrict__ Ps, const float* __restrict__ Qs,
                        float* __restrict__ H0)
{
    int tid = blockIdx.x * blockDim.x + threadIdx.x;    // NCHAN threads
    float h[DS];
#pragma unroll
    for (int n = 0; n < DS; n++) h[n] = 0.f;
    for (int c = 0; c < NCH; c++) {
        int idx = c * NCHAN + tid;
#pragma unroll
        for (int n = 0; n < DS; n++) {
            H0[n * CHTOT + idx] = h[n];
            h[n] = fmaf(Ps[n * CHTOT + idx], h[n], Qs[n * CHTOT + idx]);
        }
    }
}

// ---------------- scan pass 2: full scan with correct h0, emit y -------------
__global__ void k_scan2(const float* __restrict__ delta, const float* __restrict__ u,
                        const float* __restrict__ dbc,   const float* __restrict__ A_log,
                        const float* __restrict__ Dp,    const float* __restrict__ H0,
                        float* __restrict__ y)
{
    int flat = blockIdx.x * blockDim.x + threadIdx.x;
    int d     = flat & (DI - 1);
    int b     = (flat >> 9) & (BATCH - 1);
    int chunk = flat >> 11;

    float Av[DS];
    float4 a0 = *(const float4*)(A_log + d * DS);
    float4 a1 = *(const float4*)(A_log + d * DS + 4);
    Av[0] = -__expf(a0.x); Av[1] = -__expf(a0.y); Av[2] = -__expf(a0.z); Av[3] = -__expf(a0.w);
    Av[4] = -__expf(a1.x); Av[5] = -__expf(a1.y); Av[6] = -__expf(a1.z); Av[7] = -__expf(a1.w);

    float h[DS];
#pragma unroll
    for (int n = 0; n < DS; n++) h[n] = H0[n * CHTOT + flat];
    float Dv = Dp[d];

    int tok = b * LSEQ + chunk * TCH;
    for (int t = 0; t < TCH; t++, tok++) {
        float dl = delta[(size_t)tok * DI + d];
        float uu = u[(size_t)tok * DI + d];
        float du = dl * uu;
        const float4* Bp = (const float4*)(dbc + (size_t)tok * DBCW + DTRANK);
        float4 B0 = Bp[0], B1 = Bp[1];
        const float4* Cp = (const float4*)(dbc + (size_t)tok * DBCW + DTRANK + DS);
        float4 C0 = Cp[0], C1 = Cp[1];
        float Bv[DS] = { B0.x, B0.y, B0.z, B0.w, B1.x, B1.y, B1.z, B1.w };
        float Cv[DS] = { C0.x, C0.y, C0.z, C0.w, C1.x, C1.y, C1.z, C1.w };
        float yv = 0.f;
#pragma unroll
        for (int n = 0; n < DS; n++) {
            float a = __expf(dl * Av[n]);
            h[n] = fmaf(a, h[n], du * Bv[n]);
            yv = fmaf(h[n], Cv[n], yv);
        }
        y[(size_t)tok * DI + d] = fmaf(uu, Dv, yv);
    }
}

// ---------------- combine branches, gate with silu(z), RMSNorm ---------------
__global__ void k_rms(const float* __restrict__ yf, const float* __restrict__ yb,
                      const float* __restrict__ xz, const float* __restrict__ rw,
                      float* __restrict__ out)
{
    int tok  = blockIdx.x * 8 + (threadIdx.x >> 5);
    int lane = threadIdx.x & 31;
    int s    = tok & (LSEQ - 1);
    int rtok = tok - s + (LSEQ - 1 - s);

    float4 v[4];
    float ss = 0.f;
#pragma unroll
    for (int i = 0; i < 4; i++) {
        int d = i * 128 + lane * 4;
        float4 a = *(const float4*)(yf + (size_t)tok * DI + d);
        float4 c = *(const float4*)(yb + (size_t)rtok * DI + d);
        float4 z = *(const float4*)(xz + (size_t)tok * (2 * DI) + DI + d);
        float4 o;
        o.x = 0.5f * (a.x + c.x) * (z.x / (1.f + __expf(-z.x)));
        o.y = 0.5f * (a.y + c.y) * (z.y / (1.f + __expf(-z.y)));
        o.z = 0.5f * (a.z + c.z) * (z.z / (1.f + __expf(-z.z)));
        o.w = 0.5f * (a.w + c.w) * (z.w / (1.f + __expf(-z.w)));
        ss += o.x*o.x + o.y*o.y + o.z*o.z + o.w*o.w;
        v[i] = o;
    }
#pragma unroll
    for (int o = 16; o; o >>= 1) ss += __shfl_xor_sync(0xffffffffu, ss, o);
    float sc = rsqrtf(ss * (1.f / DI) + 1e-5f);

#pragma unroll
    for (int i = 0; i < 4; i++) {
        int d = i * 128 + lane * 4;
        float4 w4 = *(const float4*)(rw + d);
        float4 o;
        o.x = v[i].x * sc * w4.x;
        o.y = v[i].y * sc * w4.y;
        o.z = v[i].z * sc * w4.z;
        o.w = v[i].w * sc * w4.w;
        *(float4*)(out + (size_t)tok * DI + d) = o;
    }
}

// ---------------- host launch ----------------
extern "C" void kernel_launch(void* const* d_in, const int* in_sizes, int n_in,
                              void* d_out, int out_size)
{
    const float* x          = (const float*)d_in[0];
    const float* ln_w       = (const float*)d_in[1];
    const float* ln_b       = (const float*)d_in[2];
    const float* in_proj_w  = (const float*)d_in[3];
    const float* conv_w     = (const float*)d_in[4];
    const float* conv_b     = (const float*)d_in[5];
    const float* x_proj_w   = (const float*)d_in[6];
    const float* dt_proj_w  = (const float*)d_in[7];
    const float* dt_proj_b  = (const float*)d_in[8];
    const float* A_log      = (const float*)d_in[9];
    const float* Dp         = (const float*)d_in[10];
    const float* conv_w_b   = (const float*)d_in[11];
    const float* conv_b_b   = (const float*)d_in[12];
    const float* x_proj_w_b = (const float*)d_in[13];
    const float* dt_proj_w_b= (const float*)d_in[14];
    const float* dt_proj_b_b= (const float*)d_in[15];
    const float* A_log_b    = (const float*)d_in[16];
    const float* D_b        = (const float*)d_in[17];
    const float* rms_w      = (const float*)d_in[18];
    const float* out_proj_w = (const float*)d_in[19];
    float* out = (float*)d_out;

    float *hln, *xz, *xc0, *xc1, *dbc0, *dbc1, *de0, *de1, *y0, *y1, *yn;
    float *P0, *Q0, *H00, *P1, *Q1, *H01;
    cudaGetSymbolAddress((void**)&hln,  g_hln);
    cudaGetSymbolAddress((void**)&xz,   g_xz);
    cudaGetSymbolAddress((void**)&xc0,  g_xc0);
    cudaGetSymbolAddress((void**)&xc1,  g_xc1);
    cudaGetSymbolAddress((void**)&dbc0, g_dbc0);
    cudaGetSymbolAddress((void**)&dbc1, g_dbc1);
    cudaGetSymbolAddress((void**)&de0,  g_de0);
    cudaGetSymbolAddress((void**)&de1,  g_de1);
    cudaGetSymbolAddress((void**)&y0,   g_y0);
    cudaGetSymbolAddress((void**)&y1,   g_y1);
    cudaGetSymbolAddress((void**)&yn,   g_yn);
    cudaGetSymbolAddress((void**)&P0,   g_P0);
    cudaGetSymbolAddress((void**)&Q0,   g_Q0);
    cudaGetSymbolAddress((void**)&H00,  g_H00);
    cudaGetSymbolAddress((void**)&P1,   g_P1);
    cudaGetSymbolAddress((void**)&Q1,   g_Q1);
    cudaGetSymbolAddress((void**)&H01,  g_H01);

    // 1. LayerNorm
    k_layernorm<<<NTOK / 8, 256>>>(x, ln_w, ln_b, hln);

    // 2. in_proj: (16384,512) x (1024,512)^T -> xz (16384,1024)
    k_gemm<EP_NONE><<<dim3(2 * DI / BN, NTOK / BM), 256>>>(
        hln, DM, in_proj_w, xz, NTOK, 2 * DI, DM, nullptr, nullptr);

    // 3. conv + silu (fwd and reversed-bwd)
    k_conv<<<(NTOK * DI) / 256, 256>>>(xz, conv_w, conv_b, conv_w_b, conv_b_b, xc0, xc1);

    // 4. x_proj per branch: (16384,512) x (48,512)^T -> dbc (16384,48)
    k_gemm<EP_NONE><<<dim3(1, NTOK / BM), 256>>>(
        xc0, DI, x_proj_w, dbc0, NTOK, DBCW, DI, nullptr, nullptr);
    k_gemm<EP_NONE><<<dim3(1, NTOK / BM), 256>>>(
        xc1, DI, x_proj_w_b, dbc1, NTOK, DBCW, DI, nullptr, nullptr);

    // 5. dt_proj + bias + softplus: (16384,32)(lda=48) x (512,32)^T -> delta
    k_gemm<EP_SOFTPLUS><<<dim3(DI / BN, NTOK / BM), 256>>>(
        dbc0, DBCW, dt_proj_w, de0, NTOK, DI, DTRANK, dt_proj_b, nullptr);
    k_gemm<EP_SOFTPLUS><<<dim3(DI / BN, NTOK / BM), 256>>>(
        dbc1, DBCW, dt_proj_w_b, de1, NTOK, DI, DTRANK, dt_proj_b_b, nullptr);

    // 6. chunked selective scan, both branches
    k_scan1<<<CHTOT / 128, 128>>>(de0, xc0, dbc0, A_log,   P0, Q0);
    k_scan1<<<CHTOT / 128, 128>>>(de1, xc1, dbc1, A_log_b, P1, Q1);
    k_scanc<<<NCHAN / 128, 128>>>(P0, Q0, H00);
    k_scanc<<<NCHAN / 128, 128>>>(P1, Q1, H01);
    k_scan2<<<CHTOT / 128, 128>>>(de0, xc0, dbc0, A_log,   Dp,  H00, y0);
    k_scan2<<<CHTOT / 128, 128>>>(de1, xc1, dbc1, A_log_b, D_b, H01, y1);

    // 7. combine + silu(z) gate + RMSNorm
    k_rms<<<NTOK / 8, 256>>>(y0, y1, xz, rms_w, yn);

    // 8. out_proj + residual -> d_out
    k_gemm<EP_RESID><<<dim3(DM / BN, NTOK / BM), 256>>>(
        yn, DI, out_proj_w, out, NTOK, DM, DI, nullptr, x);
}

// round 3
// speedup vs baseline: 1.6799x; 1.6799x over previous
#include <cuda_runtime.h>
#include <cuda_bf16.h>
#include <cstdint>

// ---------------- problem constants ----------------
#define BATCH   4
#define LSEQ    4096
#define NTOK    (BATCH*LSEQ)       // 16384
#define DM      512
#define DI      512
#define DS      8
#define DTRANK  32
#define DBCW    48                 // DT_RANK + 2*D_STATE

// chunked scan config
#define NCH     32
#define TCH     (LSEQ/NCH)         // 128
#define NCHAN   (BATCH*DI)         // 2048
#define CHTOT   (NCHAN*NCH)        // 65536

// ---------------- scratch (device globals; no runtime alloc) ----------------
__device__ __nv_bfloat16 g_lnh[NTOK*DM];
__device__ __nv_bfloat16 g_lnl[NTOK*DM];
__device__ __nv_bfloat16 g_wih[2*DI*DM];
__device__ __nv_bfloat16 g_wil[2*DI*DM];
__device__ __nv_bfloat16 g_woh[DM*DI];
__device__ __nv_bfloat16 g_wol[DM*DI];
__device__ __nv_bfloat16 g_ynh[NTOK*DI];
__device__ __nv_bfloat16 g_ynl[NTOK*DI];
__device__ float g_xz  [NTOK*2*DI];
__device__ float g_xc0 [NTOK*DI];
__device__ float g_xc1 [NTOK*DI];
__device__ float g_dbc0[NTOK*DBCW];
__device__ float g_dbc1[NTOK*DBCW];
__device__ float g_de0 [NTOK*DI];
__device__ float g_de1 [NTOK*DI];
__device__ float g_y0  [NTOK*DI];
__device__ float g_y1  [NTOK*DI];
__device__ float g_P0  [DS*CHTOT];
__device__ float g_Q0  [DS*CHTOT];
__device__ float g_H00 [DS*CHTOT];
__device__ float g_P1  [DS*CHTOT];
__device__ float g_Q1  [DS*CHTOT];
__device__ float g_H01 [DS*CHTOT];

// ---------------- helpers ----------------
__device__ __forceinline__ uint32_t smem_u32(const void* p) {
    uint32_t a;
    asm("{ .reg .u64 t; cvta.to.shared.u64 t, %1; cvt.u32.u64 %0, t; }" : "=r"(a) : "l"(p));
    return a;
}
__device__ __forceinline__ void ldsm4(uint32_t* r, uint32_t addr) {
    asm volatile("ldmatrix.sync.aligned.m8n8.x4.shared.b16 {%0,%1,%2,%3}, [%4];"
        : "=r"(r[0]), "=r"(r[1]), "=r"(r[2]), "=r"(r[3]) : "r"(addr));
}
__device__ __forceinline__ void mma16816(float* c, const uint32_t* a, const uint32_t* b) {
    asm volatile("mma.sync.aligned.m16n8k16.row.col.f32.bf16.bf16.f32 "
        "{%0,%1,%2,%3},{%4,%5,%6,%7},{%8,%9},{%0,%1,%2,%3};"
        : "+f"(c[0]), "+f"(c[1]), "+f"(c[2]), "+f"(c[3])
        : "r"(a[0]), "r"(a[1]), "r"(a[2]), "r"(a[3]), "r"(b[0]), "r"(b[1]));
}

// ---------------- mma.sync split-bf16 GEMM ----------------
// C[M,N] = A[M,512] * W[N,512]^T (+resid).  A,W given as bf16 hi/lo pairs.
// Tile 128x128, K-chunk 64 (128B rows, xor-8 swizzle), cp.async double buffer.
#define KCH     64
#define NKCH    (512/KCH)          // 8
#define TILEB   16384              // one 128x64 bf16 tile in smem
#define STG_SZ  (4*TILEB)          // Ah, Al, Bh, Bl
#define MMA_SMEM (2*STG_SZ)        // 131072

__device__ __forceinline__ void mma_load_chunk(
    const __nv_bfloat16* __restrict__ Ah, const __nv_bfloat16* __restrict__ Al,
    const __nv_bfloat16* __restrict__ Bh, const __nv_bfloat16* __restrict__ Bl,
    int m0, int n0, int kc, uint32_t stage)
{
    const int t = threadIdx.x;
#pragma unroll
    for (int it = 0; it < 16; it++) {
        int idx   = it * 256 + t;          // 0..4095 chunk16 loads
        int tile  = idx >> 10;             // 0:Ah 1:Al 2:Bh 3:Bl
        int local = idx & 1023;
        int row   = local >> 3;
        int c     = local & 7;
        const __nv_bfloat16* gb = (tile == 0) ? Ah : (tile == 1) ? Al : (tile == 2) ? Bh : Bl;
        int base = (tile < 2) ? m0 : n0;
        const void* ga = gb + (size_t)(base + row) * 512 + kc * KCH + c * 8;
        uint32_t sa = stage + tile * TILEB + row * 128 + ((c ^ (row & 7)) << 4);
        asm volatile("cp.async.cg.shared.global [%0], [%1], 16;" :: "r"(sa), "l"(ga));
    }
}

template<bool RESID>
__global__ __launch_bounds__(256)
void k_mma(const __nv_bfloat16* __restrict__ Ah, const __nv_bfloat16* __restrict__ Al,
           const __nv_bfloat16* __restrict__ Bh, const __nv_bfloat16* __restrict__ Bl,
           float* __restrict__ C, int N, const float* __restrict__ resid)
{
    extern __shared__ __align__(128) char smem[];
    const uint32_t sb = smem_u32(smem);
    const int m0 = blockIdx.y * 128;
    const int n0 = blockIdx.x * 128;
    const int w  = threadIdx.x >> 5;
    const int lane = threadIdx.x & 31;
    const int wm = (w >> 2) * 64;      // warp M offset within tile
    const int wn = (w & 3) * 32;       // warp N offset

    float acc[4][4][4];
#pragma unroll
    for (int i = 0; i < 4; i++)
#pragma unroll
        for (int j = 0; j < 4; j++)
#pragma unroll
            for (int q = 0; q < 4; q++) acc[i][j][q] = 0.f;

    // ldmatrix per-thread addressing constants
    const int ar  = lane & 15;         // A row within 16
    const int ach = lane >> 4;         // A k-half
    const int bt8 = lane & 7;
    const int bg  = lane >> 3;
    const int bn8 = (bg >> 1) << 3;    // +8 for groups 2,3
    const int bch = bg & 1;

    // prologue
    mma_load_chunk(Ah, Al, Bh, Bl, m0, n0, 0, sb);
    asm volatile("cp.async.commit_group;");
    mma_load_chunk(Ah, Al, Bh, Bl, m0, n0, 1, sb + STG_SZ);
    asm volatile("cp.async.commit_group;");

    for (int i = 0; i < NKCH; i++) {
        if (i < NKCH - 1) asm volatile("cp.async.wait_group 1;");
        else              asm volatile("cp.async.wait_group 0;");
        __syncthreads();

        const uint32_t stg = sb + (i & 1) * STG_SZ;
        const uint32_t sAh = stg, sAl = stg + TILEB, sBh = stg + 2*TILEB, sBl = stg + 3*TILEB;

#pragma unroll
        for (int ks = 0; ks < 4; ks++) {
            uint32_t ah[4][4], al[4][4], bh[2][4], bl[2][4];
#pragma unroll
            for (int mi = 0; mi < 4; mi++) {
                int r = wm + mi * 16 + ar;
                int c = ks * 2 + ach;
                uint32_t off = r * 128 + (((uint32_t)(c ^ (r & 7))) << 4);
                ldsm4(ah[mi], sAh + off);
                ldsm4(al[mi], sAl + off);
            }
#pragma unroll
            for (int ni = 0; ni < 2; ni++) {
                int n = wn + ni * 16 + bn8 + bt8;
                int c = ks * 2 + bch;
                uint32_t off = n * 128 + (((uint32_t)(c ^ (n & 7))) << 4);
                ldsm4(bh[ni], sBh + off);
                ldsm4(bl[ni], sBl + off);
            }
#pragma unroll
            for (int mi = 0; mi < 4; mi++)
#pragma unroll
                for (int nj = 0; nj < 4; nj++) {
                    const uint32_t* bhp = &bh[nj >> 1][(nj & 1) * 2];
                    const uint32_t* blp = &bl[nj >> 1][(nj & 1) * 2];
                    mma16816(acc[mi][nj], ah[mi], bhp);
                    mma16816(acc[mi][nj], ah[mi], blp);
                    mma16816(acc[mi][nj], al[mi], bhp);
                }
        }

        if (i < NKCH - 2) {
            __syncthreads();
            mma_load_chunk(Ah, Al, Bh, Bl, m0, n0, i + 2, stg);
            asm volatile("cp.async.commit_group;");
        }
    }

    // epilogue
#pragma unroll
    for (int mi = 0; mi < 4; mi++) {
        int m = m0 + wm + mi * 16 + (lane >> 2);
#pragma unroll
        for (int nj = 0; nj < 4; nj++) {
            int n = n0 + wn + nj * 8 + ((lane & 3) << 1);
            float2 v0 = make_float2(acc[mi][nj][0], acc[mi][nj][1]);
            float2 v1 = make_float2(acc[mi][nj][2], acc[mi][nj][3]);
            if (RESID) {
                float2 r0 = *(const float2*)(resid + (size_t)m * N + n);
                float2 r1 = *(const float2*)(resid + (size_t)(m + 8) * N + n);
                v0.x += r0.x; v0.y += r0.y; v1.x += r1.x; v1.y += r1.y;
            }
            *(float2*)(C + (size_t)m * N + n)       = v0;
            *(float2*)(C + (size_t)(m + 8) * N + n) = v1;
        }
    }
}

// ---------------- fp32 -> bf16 hi/lo weight convert ----------------
__global__ void k_cvt(const float* __restrict__ w, __nv_bfloat16* __restrict__ hi,
                      __nv_bfloat16* __restrict__ lo, int n)
{
    int i = blockIdx.x * blockDim.x + threadIdx.x;
    if (i < n) {
        float v = w[i];
        __nv_bfloat16 h = __float2bfloat16(v);
        hi[i] = h;
        lo[i] = __float2bfloat16(v - __bfloat162float(h));
    }
}

// ---------------- LayerNorm -> bf16 hi/lo ----------------
__global__ void k_layernorm(const float* __restrict__ x,
                            const float* __restrict__ w,
                            const float* __restrict__ b,
                            __nv_bfloat16* __restrict__ oh,
                            __nv_bfloat16* __restrict__ ol)
{
    int tok  = blockIdx.x * 8 + (threadIdx.x >> 5);
    int lane = threadIdx.x & 31;
    const float* row = x + (size_t)tok * DM;

    float4 v[4];
    float s = 0.f, s2 = 0.f;
#pragma unroll
    for (int i = 0; i < 4; i++) {
        v[i] = *(const float4*)(row + i * 128 + lane * 4);
        s  += v[i].x + v[i].y + v[i].z + v[i].w;
        s2 += v[i].x*v[i].x + v[i].y*v[i].y + v[i].z*v[i].z + v[i].w*v[i].w;
    }
#pragma unroll
    for (int o = 16; o; o >>= 1) {
        s  += __shfl_xor_sync(0xffffffffu, s,  o);
        s2 += __shfl_xor_sync(0xffffffffu, s2, o);
    }
    float mu   = s * (1.f / DM);
    float var  = s2 * (1.f / DM) - mu * mu;
    float rinv = rsqrtf(var + 1e-5f);

#pragma unroll
    for (int i = 0; i < 4; i++) {
        int d = i * 128 + lane * 4;
        float4 w4 = *(const float4*)(w + d);
        float4 b4 = *(const float4*)(b + d);
        float o4[4];
        o4[0] = (v[i].x - mu) * rinv * w4.x + b4.x;
        o4[1] = (v[i].y - mu) * rinv * w4.y + b4.y;
        o4[2] = (v[i].z - mu) * rinv * w4.z + b4.z;
        o4[3] = (v[i].w - mu) * rinv * w4.w + b4.w;
        __nv_bfloat16 hh[4], ll[4];
#pragma unroll
        for (int q = 0; q < 4; q++) {
            hh[q] = __float2bfloat16(o4[q]);
            ll[q] = __float2bfloat16(o4[q] - __bfloat162float(hh[q]));
        }
        *(uint2*)(oh + (size_t)tok * DM + d) = *(uint2*)hh;
        *(uint2*)(ol + (size_t)tok * DM + d) = *(uint2*)ll;
    }
}

// ---------------- batched SGEMM (both branches via blockIdx.z) ----------------
#define BM 64
#define BN 64
#define BKK 16
enum { EP_NONE = 0, EP_SOFTPLUS = 1 };

template<int EPI>
__global__ __launch_bounds__(256)
void k_gemm2(const float* __restrict__ A0, const float* __restrict__ A1, int lda,
             const float* __restrict__ W0, const float* __restrict__ W1,
             float* __restrict__ C0, float* __restrict__ C1,
             int M, int N, int K,
             const float* __restrict__ bias0, const float* __restrict__ bias1)
{
    const float* A = blockIdx.z ? A1 : A0;
    const float* W = blockIdx.z ? W1 : W0;
    float* C = blockIdx.z ? C1 : C0;
    const float* bias = blockIdx.z ? bias1 : bias0;

    __shared__ __align__(16) float As[BKK][BM + 4];
    __shared__ __align__(16) float Ws[BKK][BN + 4];

    const int bm = blockIdx.y * BM;
    const int bn = blockIdx.x * BN;
    const int tid = threadIdx.x;
    const int tx = tid & 15;
    const int ty = tid >> 4;
    const int lr = tid >> 2;
    const int lq = tid & 3;

    float acc[4][4];
#pragma unroll
    for (int i = 0; i < 4; i++)
#pragma unroll
        for (int j = 0; j < 4; j++) acc[i][j] = 0.f;

    const bool wok = (bn + lr) < N;
    const float* Ap = A + (size_t)(bm + lr) * lda + lq * 4;
    const float* Wp = W + (size_t)(wok ? (bn + lr) : 0) * K + lq * 4;

    for (int k0 = 0; k0 < K; k0 += BKK) {
        float4 av = *(const float4*)(Ap + k0);
        float4 wv = wok ? *(const float4*)(Wp + k0) : make_float4(0.f, 0.f, 0.f, 0.f);
        __syncthreads();
        As[lq*4+0][lr] = av.x; As[lq*4+1][lr] = av.y;
        As[lq*4+2][lr] = av.z; As[lq*4+3][lr] = av.w;
        Ws[lq*4+0][lr] = wv.x; Ws[lq*4+1][lr] = wv.y;
        Ws[lq*4+2][lr] = wv.z; Ws[lq*4+3][lr] = wv.w;
        __syncthreads();
#pragma unroll
        for (int kk = 0; kk < BKK; kk++) {
            float4 ra = *(const float4*)(&As[kk][ty * 4]);
            float4 rw = *(const float4*)(&Ws[kk][tx * 4]);
            float a4[4] = { ra.x, ra.y, ra.z, ra.w };
            float w4[4] = { rw.x, rw.y, rw.z, rw.w };
#pragma unroll
            for (int i = 0; i < 4; i++)
#pragma unroll
                for (int j = 0; j < 4; j++)
                    acc[i][j] = fmaf(a4[i], w4[j], acc[i][j]);
        }
    }

#pragma unroll
    for (int i = 0; i < 4; i++) {
        int m = bm + ty * 4 + i;
#pragma unroll
        for (int j = 0; j < 4; j++) {
            int n = bn + tx * 4 + j;
            if (n < N) {
                float v = acc[i][j];
                if (EPI == EP_SOFTPLUS) {
                    v += bias[n];
                    v = (v > 20.f) ? v : log1pf(__expf(v));
                }
                C[(size_t)m * N + n] = v;
            }
        }
    }
}

// ---------------- causal depthwise conv (k=2) + SiLU, fwd + reversed-bwd ------
__global__ void k_conv(const float* __restrict__ xz,
                       const float* __restrict__ cw,  const float* __restrict__ cb,
                       const float* __restrict__ cwb, const float* __restrict__ cbb,
                       float* __restrict__ xcf, float* __restrict__ xcb)
{
    int flat = blockIdx.x * blockDim.x + threadIdx.x;
    int d   = flat & (DI - 1);
    int tok = flat >> 9;
    int b   = tok >> 12;
    int s   = tok & (LSEQ - 1);

    float xcur = xz[(size_t)tok * (2 * DI) + d];
    float xprv = (s > 0) ? xz[(size_t)(tok - 1) * (2 * DI) + d] : 0.f;
    float vf = fmaf(cw[d * 2 + 0], xprv, fmaf(cw[d * 2 + 1], xcur, cb[d]));
    xcf[flat] = vf / (1.f + __expf(-vf));

    int t1 = b * LSEQ + (LSEQ - 1 - s);
    float xcb_cur = xz[(size_t)t1 * (2 * DI) + d];
    float xcb_prv = (s > 0) ? xz[(size_t)(t1 + 1) * (2 * DI) + d] : 0.f;
    float vb = fmaf(cwb[d * 2 + 0], xcb_prv, fmaf(cwb[d * 2 + 1], xcb_cur, cbb[d]));
    xcb[flat] = vb / (1.f + __expf(-vb));
}

// ---------------- scan pass 1 ----------------
__global__ void k_scan1(const float* __restrict__ delta, const float* __restrict__ u,
                        const float* __restrict__ dbc,   const float* __restrict__ A_log,
                        float* __restrict__ Ps, float* __restrict__ Qs)
{
    int flat = blockIdx.x * blockDim.x + threadIdx.x;
    int d     = flat & (DI - 1);
    int b     = (flat >> 9) & (BATCH - 1);
    int chunk = flat >> 11;

    float Av[DS];
    float4 a0 = *(const float4*)(A_log + d * DS);
    float4 a1 = *(const float4*)(A_log + d * DS + 4);
    Av[0] = -__expf(a0.x); Av[1] = -__expf(a0.y); Av[2] = -__expf(a0.z); Av[3] = -__expf(a0.w);
    Av[4] = -__expf(a1.x); Av[5] = -__expf(a1.y); Av[6] = -__expf(a1.z); Av[7] = -__expf(a1.w);

    float h[DS], P[DS];
#pragma unroll
    for (int n = 0; n < DS; n++) { h[n] = 0.f; P[n] = 1.f; }

    int tok = b * LSEQ + chunk * TCH;
    for (int t = 0; t < TCH; t++, tok++) {
        float dl = delta[(size_t)tok * DI + d];
        float uu = u[(size_t)tok * DI + d];
        float du = dl * uu;
        const float4* Bp = (const float4*)(dbc + (size_t)tok * DBCW + DTRANK);
        float4 B0 = Bp[0], B1 = Bp[1];
        float Bv[DS] = { B0.x, B0.y, B0.z, B0.w, B1.x, B1.y, B1.z, B1.w };
#pragma unroll
        for (int n = 0; n < DS; n++) {
            float a = __expf(dl * Av[n]);
            P[n] *= a;
            h[n] = fmaf(a, h[n], du * Bv[n]);
        }
    }
#pragma unroll
    for (int n = 0; n < DS; n++) {
        Ps[n * CHTOT + flat] = P[n];
        Qs[n * CHTOT + flat] = h[n];
    }
}

// ---------------- scan combine ----------------
__global__ void k_scanc(const float* __restrict__ Ps, const float* __restrict__ Qs,
                        float* __restrict__ H0)
{
    int tid = blockIdx.x * blockDim.x + threadIdx.x;
    float h[DS];
#pragma unroll
    for (int n = 0; n < DS; n++) h[n] = 0.f;
    for (int c = 0; c < NCH; c++) {
        int idx = c * NCHAN + tid;
#pragma unroll
        for (int n = 0; n < DS; n++) {
            H0[n * CHTOT + idx] = h[n];
            h[n] = fmaf(Ps[n * CHTOT + idx], h[n], Qs[n * CHTOT + idx]);
        }
    }
}

// ---------------- scan pass 2 ----------------
__global__ void k_scan2(const float* __restrict__ delta, const float* __restrict__ u,
                        const float* __restrict__ dbc,   const float* __restrict__ A_log,
                        const float* __restrict__ Dp,    const float* __restrict__ H0,
                        float* __restrict__ y)
{
    int flat = blockIdx.x * blockDim.x + threadIdx.x;
    int d     = flat & (DI - 1);
    int b     = (flat >> 9) & (BATCH - 1);
    int chunk = flat >> 11;

    float Av[DS];
    float4 a0 = *(const float4*)(A_log + d * DS);
    float4 a1 = *(const float4*)(A_log + d * DS + 4);
    Av[0] = -__expf(a0.x); Av[1] = -__expf(a0.y); Av[2] = -__expf(a0.z); Av[3] = -__expf(a0.w);
    Av[4] = -__expf(a1.x); Av[5] = -__expf(a1.y); Av[6] = -__expf(a1.z); Av[7] = -__expf(a1.w);

    float h[DS];
#pragma unroll
    for (int n = 0; n < DS; n++) h[n] = H0[n * CHTOT + flat];
    float Dv = Dp[d];

    int tok = b * LSEQ + chunk * TCH;
    for (int t = 0; t < TCH; t++, tok++) {
        float dl = delta[(size_t)tok * DI + d];
        float uu = u[(size_t)tok * DI + d];
        float du = dl * uu;
        const float4* Bp = (const float4*)(dbc + (size_t)tok * DBCW + DTRANK);
        float4 B0 = Bp[0], B1 = Bp[1];
        const float4* Cp = (const float4*)(dbc + (size_t)tok * DBCW + DTRANK + DS);
        float4 C0 = Cp[0], C1 = Cp[1];
        float Bv[DS] = { B0.x, B0.y, B0.z, B0.w, B1.x, B1.y, B1.z, B1.w };
        float Cv[DS] = { C0.x, C0.y, C0.z, C0.w, C1.x, C1.y, C1.z, C1.w };
        float yv = 0.f;
#pragma unroll
        for (int n = 0; n < DS; n++) {
            float a = __expf(dl * Av[n]);
            h[n] = fmaf(a, h[n], du * Bv[n]);
            yv = fmaf(h[n], Cv[n], yv);
        }
        y[(size_t)tok * DI + d] = fmaf(uu, Dv, yv);
    }
}

// ---------------- combine branches, gate, RMSNorm -> bf16 hi/lo ---------------
__global__ void k_rms(const float* __restrict__ yf, const float* __restrict__ yb,
                      const float* __restrict__ xz, const float* __restrict__ rw,
                      __nv_bfloat16* __restrict__ oh, __nv_bfloat16* __restrict__ ol)
{
    int tok  = blockIdx.x * 8 + (threadIdx.x >> 5);
    int lane = threadIdx.x & 31;
    int s    = tok & (LSEQ - 1);
    int rtok = tok - s + (LSEQ - 1 - s);

    float4 v[4];
    float ss = 0.f;
#pragma unroll
    for (int i = 0; i < 4; i++) {
        int d = i * 128 + lane * 4;
        float4 a = *(const float4*)(yf + (size_t)tok * DI + d);
        float4 c = *(const float4*)(yb + (size_t)rtok * DI + d);
        float4 z = *(const float4*)(xz + (size_t)tok * (2 * DI) + DI + d);
        float4 o;
        o.x = 0.5f * (a.x + c.x) * (z.x / (1.f + __expf(-z.x)));
        o.y = 0.5f * (a.y + c.y) * (z.y / (1.f + __expf(-z.y)));
        o.z = 0.5f * (a.z + c.z) * (z.z / (1.f + __expf(-z.z)));
        o.w = 0.5f * (a.w + c.w) * (z.w / (1.f + __expf(-z.w)));
        ss += o.x*o.x + o.y*o.y + o.z*o.z + o.w*o.w;
        v[i] = o;
    }
#pragma unroll
    for (int o = 16; o; o >>= 1) ss += __shfl_xor_sync(0xffffffffu, ss, o);
    float sc = rsqrtf(ss * (1.f / DI) + 1e-5f);

#pragma unroll
    for (int i = 0; i < 4; i++) {
        int d = i * 128 + lane * 4;
        float4 w4 = *(const float4*)(rw + d);
        float o4[4];
        o4[0] = v[i].x * sc * w4.x;
        o4[1] = v[i].y * sc * w4.y;
        o4[2] = v[i].z * sc * w4.z;
        o4[3] = v[i].w * sc * w4.w;
        __nv_bfloat16 hh[4], ll[4];
#pragma unroll
        for (int q = 0; q < 4; q++) {
            hh[q] = __float2bfloat16(o4[q]);
            ll[q] = __float2bfloat16(o4[q] - __bfloat162float(hh[q]));
        }
        *(uint2*)(oh + (size_t)tok * DI + d) = *(uint2*)hh;
        *(uint2*)(ol + (size_t)tok * DI + d) = *(uint2*)ll;
    }
}

// ---------------- host launch ----------------
extern "C" void kernel_launch(void* const* d_in, const int* in_sizes, int n_in,
                              void* d_out, int out_size)
{
    const float* x          = (const float*)d_in[0];
    const float* ln_w       = (const float*)d_in[1];
    const float* ln_b       = (const float*)d_in[2];
    const float* in_proj_w  = (const float*)d_in[3];
    const float* conv_w     = (const float*)d_in[4];
    const float* conv_b     = (const float*)d_in[5];
    const float* x_proj_w   = (const float*)d_in[6];
    const float* dt_proj_w  = (const float*)d_in[7];
    const float* dt_proj_b  = (const float*)d_in[8];
    const float* A_log      = (const float*)d_in[9];
    const float* Dp         = (const float*)d_in[10];
    const float* conv_w_b   = (const float*)d_in[11];
    const float* conv_b_b   = (const float*)d_in[12];
    const float* x_proj_w_b = (const float*)d_in[13];
    const float* dt_proj_w_b= (const float*)d_in[14];
    const float* dt_proj_b_b= (const float*)d_in[15];
    const float* A_log_b    = (const float*)d_in[16];
    const float* D_b        = (const float*)d_in[17];
    const float* rms_w      = (const float*)d_in[18];
    const float* out_proj_w = (const float*)d_in[19];
    float* out = (float*)d_out;

    __nv_bfloat16 *lnh, *lnl, *wih, *wil, *woh, *wol, *ynh, *ynl;
    float *xz, *xc0, *xc1, *dbc0, *dbc1, *de0, *de1, *y0, *y1;
    float *P0, *Q0, *H00, *P1, *Q1, *H01;
    cudaGetSymbolAddress((void**)&lnh,  g_lnh);
    cudaGetSymbolAddress((void**)&lnl,  g_lnl);
    cudaGetSymbolAddress((void**)&wih,  g_wih);
    cudaGetSymbolAddress((void**)&wil,  g_wil);
    cudaGetSymbolAddress((void**)&woh,  g_woh);
    cudaGetSymbolAddress((void**)&wol,  g_wol);
    cudaGetSymbolAddress((void**)&ynh,  g_ynh);
    cudaGetSymbolAddress((void**)&ynl,  g_ynl);
    cudaGetSymbolAddress((void**)&xz,   g_xz);
    cudaGetSymbolAddress((void**)&xc0,  g_xc0);
    cudaGetSymbolAddress((void**)&xc1,  g_xc1);
    cudaGetSymbolAddress((void**)&dbc0, g_dbc0);
    cudaGetSymbolAddress((void**)&dbc1, g_dbc1);
    cudaGetSymbolAddress((void**)&de0,  g_de0);
    cudaGetSymbolAddress((void**)&de1,  g_de1);
    cudaGetSymbolAddress((void**)&y0,   g_y0);
    cudaGetSymbolAddress((void**)&y1,   g_y1);
    cudaGetSymbolAddress((void**)&P0,   g_P0);
    cudaGetSymbolAddress((void**)&Q0,   g_Q0);
    cudaGetSymbolAddress((void**)&H00,  g_H00);
    cudaGetSymbolAddress((void**)&P1,   g_P1);
    cudaGetSymbolAddress((void**)&Q1,   g_Q1);
    cudaGetSymbolAddress((void**)&H01,  g_H01);

    cudaFuncSetAttribute(k_mma<false>, cudaFuncAttributeMaxDynamicSharedMemorySize, MMA_SMEM);
    cudaFuncSetAttribute(k_mma<true>,  cudaFuncAttributeMaxDynamicSharedMemorySize, MMA_SMEM);

    // 0. convert weights to bf16 hi/lo
    k_cvt<<<(2*DI*DM + 255)/256, 256>>>(in_proj_w,  wih, wil, 2*DI*DM);
    k_cvt<<<(DM*DI   + 255)/256, 256>>>(out_proj_w, woh, wol, DM*DI);

    // 1. LayerNorm -> bf16 hi/lo
    k_layernorm<<<NTOK / 8, 256>>>(x, ln_w, ln_b, lnh, lnl);

    // 2. in_proj (mma.sync split-bf16): (16384,512) x (1024,512)^T -> xz fp32
    k_mma<false><<<dim3(2*DI/128, NTOK/128), 256, MMA_SMEM>>>(lnh, lnl, wih, wil, xz, 2*DI, nullptr);

    // 3. conv + silu (fwd and reversed-bwd)
    k_conv<<<(NTOK * DI) / 256, 256>>>(xz, conv_w, conv_b, conv_w_b, conv_b_b, xc0, xc1);

    // 4. x_proj both branches: (16384,512) x (48,512)^T -> dbc (16384,48)
    k_gemm2<EP_NONE><<<dim3(1, NTOK/BM, 2), 256>>>(
        xc0, xc1, DI, x_proj_w, x_proj_w_b, dbc0, dbc1, NTOK, DBCW, DI, nullptr, nullptr);

    // 5. dt_proj + bias + softplus, both branches
    k_gemm2<EP_SOFTPLUS><<<dim3(DI/BN, NTOK/BM, 2), 256>>>(
        dbc0, dbc1, DBCW, dt_proj_w, dt_proj_w_b, de0, de1, NTOK, DI, DTRANK,
        dt_proj_b, dt_proj_b_b);

    // 6. chunked selective scan, both branches
    k_scan1<<<CHTOT / 128, 128>>>(de0, xc0, dbc0, A_log,   P0, Q0);
    k_scan1<<<CHTOT / 128, 128>>>(de1, xc1, dbc1, A_log_b, P1, Q1);
    k_scanc<<<NCHAN / 128, 128>>>(P0, Q0, H00);
    k_scanc<<<NCHAN / 128, 128>>>(P1, Q1, H01);
    k_scan2<<<CHTOT / 128, 128>>>(de0, xc0, dbc0, A_log,   Dp,  H00, y0);
    k_scan2<<<CHTOT / 128, 128>>>(de1, xc1, dbc1, A_log_b, D_b, H01, y1);

    // 7. combine + silu(z) gate + RMSNorm -> bf16 hi/lo
    k_rms<<<NTOK / 8, 256>>>(y0, y1, xz, rms_w, ynh, ynl);

    // 8. out_proj (mma.sync split-bf16) + residual -> d_out
    k_mma<true><<<dim3(DM/128, NTOK/128), 256, MMA_SMEM>>>(ynh, ynl, woh, wol, out, DM, x);
}

// round 4
// speedup vs baseline: 1.7126x; 1.0195x over previous
#include <cuda_runtime.h>
#include <cuda_bf16.h>
#include <cstdint>

// ---------------- problem constants ----------------
#define BATCH   4
#define LSEQ    4096
#define NTOK    (BATCH*LSEQ)       // 16384
#define DM      512
#define DI      512
#define DS      8
#define DTRANK  32
#define DBCW    48                 // DT_RANK + 2*D_STATE

// chunked scan config
#define NCH     32
#define TCH     (LSEQ/NCH)         // 128
#define NCHAN   (BATCH*DI)         // 2048
#define CHTOT   (NCHAN*NCH)        // 65536

// ---------------- scratch (device globals; no runtime alloc) ----------------
__device__ __nv_bfloat16 g_lnh[NTOK*DM];
__device__ __nv_bfloat16 g_lnl[NTOK*DM];
__device__ __nv_bfloat16 g_wih[2*DI*DM];
__device__ __nv_bfloat16 g_wil[2*DI*DM];
__device__ __nv_bfloat16 g_woh[DM*DI];
__device__ __nv_bfloat16 g_wol[DM*DI];
__device__ __nv_bfloat16 g_ynh[NTOK*DI];
__device__ __nv_bfloat16 g_ynl[NTOK*DI];
__device__ float g_xz  [NTOK*2*DI];
__device__ float g_xc0 [NTOK*DI];
__device__ float g_xc1 [NTOK*DI];
__device__ float g_dbc0[NTOK*DBCW];
__device__ float g_dbc1[NTOK*DBCW];
__device__ float g_y0  [NTOK*DI];
__device__ float g_y1  [NTOK*DI];
__device__ float g_P0  [DS*CHTOT];
__device__ float g_Q0  [DS*CHTOT];
__device__ float g_P1  [DS*CHTOT];
__device__ float g_Q1  [DS*CHTOT];
__device__ int   g_flags[1024];

// ---------------- helpers ----------------
__device__ __forceinline__ uint32_t smem_u32(const void* p) {
    uint32_t a;
    asm("{ .reg .u64 t; cvta.to.shared.u64 t, %1; cvt.u32.u64 %0, t; }" : "=r"(a) : "l"(p));
    return a;
}
__device__ __forceinline__ void ldsm4(uint32_t* r, uint32_t addr) {
    asm volatile("ldmatrix.sync.aligned.m8n8.x4.shared.b16 {%0,%1,%2,%3}, [%4];"
        : "=r"(r[0]), "=r"(r[1]), "=r"(r[2]), "=r"(r[3]) : "r"(addr));
}
__device__ __forceinline__ void mma16816(float* c, const uint32_t* a, const uint32_t* b) {
    asm volatile("mma.sync.aligned.m16n8k16.row.col.f32.bf16.bf16.f32 "
        "{%0,%1,%2,%3},{%4,%5,%6,%7},{%8,%9},{%0,%1,%2,%3};"
        : "+f"(c[0]), "+f"(c[1]), "+f"(c[2]), "+f"(c[3])
        : "r"(a[0]), "r"(a[1]), "r"(a[2]), "r"(a[3]), "r"(b[0]), "r"(b[1]));
}

// ---------------- mma.sync split-bf16 GEMM ----------------
#define KCH     64
#define NKCH    (512/KCH)          // 8
#define TILEB   16384              // one 128x64 bf16 tile in smem
#define STG_SZ  (4*TILEB)          // Ah, Al, Bh, Bl
#define MMA_SMEM (2*STG_SZ)        // 131072

__device__ __forceinline__ void mma_load_chunk(
    const __nv_bfloat16* __restrict__ Ah, const __nv_bfloat16* __restrict__ Al,
    const __nv_bfloat16* __restrict__ Bh, const __nv_bfloat16* __restrict__ Bl,
    int m0, int n0, int kc, uint32_t stage)
{
    const int t = threadIdx.x;
#pragma unroll
    for (int it = 0; it < 16; it++) {
        int idx   = it * 256 + t;
        int tile  = idx >> 10;             // 0:Ah 1:Al 2:Bh 3:Bl
        int local = idx & 1023;
        int row   = local >> 3;
        int c     = local & 7;
        const __nv_bfloat16* gb = (tile == 0) ? Ah : (tile == 1) ? Al : (tile == 2) ? Bh : Bl;
        int base = (tile < 2) ? m0 : n0;
        const void* ga = gb + (size_t)(base + row) * 512 + kc * KCH + c * 8;
        uint32_t sa = stage + tile * TILEB + row * 128 + ((c ^ (row & 7)) << 4);
        asm volatile("cp.async.cg.shared.global [%0], [%1], 16;" :: "r"(sa), "l"(ga));
    }
}

template<bool RESID>
__global__ __launch_bounds__(256)
void k_mma(const __nv_bfloat16* __restrict__ Ah, const __nv_bfloat16* __restrict__ Al,
           const __nv_bfloat16* __restrict__ Bh, const __nv_bfloat16* __restrict__ Bl,
           float* __restrict__ C, int N, const float* __restrict__ resid)
{
    extern __shared__ __align__(128) char smem[];
    const uint32_t sb = smem_u32(smem);
    const int m0 = blockIdx.y * 128;
    const int n0 = blockIdx.x * 128;
    const int w  = threadIdx.x >> 5;
    const int lane = threadIdx.x & 31;
    const int wm = (w >> 2) * 64;
    const int wn = (w & 3) * 32;

    float acc[4][4][4];
#pragma unroll
    for (int i = 0; i < 4; i++)
#pragma unroll
        for (int j = 0; j < 4; j++)
#pragma unroll
            for (int q = 0; q < 4; q++) acc[i][j][q] = 0.f;

    const int ar  = lane & 15;
    const int ach = lane >> 4;
    const int bt8 = lane & 7;
    const int bg  = lane >> 3;
    const int bn8 = (bg >> 1) << 3;
    const int bch = bg & 1;

    mma_load_chunk(Ah, Al, Bh, Bl, m0, n0, 0, sb);
    asm volatile("cp.async.commit_group;");
    mma_load_chunk(Ah, Al, Bh, Bl, m0, n0, 1, sb + STG_SZ);
    asm volatile("cp.async.commit_group;");

    for (int i = 0; i < NKCH; i++) {
        if (i < NKCH - 1) asm volatile("cp.async.wait_group 1;");
        else              asm volatile("cp.async.wait_group 0;");
        __syncthreads();

        const uint32_t stg = sb + (i & 1) * STG_SZ;
        const uint32_t sAh = stg, sAl = stg + TILEB, sBh = stg + 2*TILEB, sBl = stg + 3*TILEB;

#pragma unroll
        for (int ks = 0; ks < 4; ks++) {
            uint32_t ah[4][4], al[4][4], bh[2][4], bl[2][4];
#pragma unroll
            for (int mi = 0; mi < 4; mi++) {
                int r = wm + mi * 16 + ar;
                int c = ks * 2 + ach;
                uint32_t off = r * 128 + (((uint32_t)(c ^ (r & 7))) << 4);
                ldsm4(ah[mi], sAh + off);
                ldsm4(al[mi], sAl + off);
            }
#pragma unroll
            for (int ni = 0; ni < 2; ni++) {
                int n = wn + ni * 16 + bn8 + bt8;
                int c = ks * 2 + bch;
                uint32_t off = n * 128 + (((uint32_t)(c ^ (n & 7))) << 4);
                ldsm4(bh[ni], sBh + off);
                ldsm4(bl[ni], sBl + off);
            }
#pragma unroll
            for (int mi = 0; mi < 4; mi++)
#pragma unroll
                for (int nj = 0; nj < 4; nj++) {
                    const uint32_t* bhp = &bh[nj >> 1][(nj & 1) * 2];
                    const uint32_t* blp = &bl[nj >> 1][(nj & 1) * 2];
                    mma16816(acc[mi][nj], ah[mi], bhp);
                    mma16816(acc[mi][nj], ah[mi], blp);
                    mma16816(acc[mi][nj], al[mi], bhp);
                }
        }

        if (i < NKCH - 2) {
            __syncthreads();
            mma_load_chunk(Ah, Al, Bh, Bl, m0, n0, i + 2, stg);
            asm volatile("cp.async.commit_group;");
        }
    }

#pragma unroll
    for (int mi = 0; mi < 4; mi++) {
        int m = m0 + wm + mi * 16 + (lane >> 2);
#pragma unroll
        for (int nj = 0; nj < 4; nj++) {
            int n = n0 + wn + nj * 8 + ((lane & 3) << 1);
            float2 v0 = make_float2(acc[mi][nj][0], acc[mi][nj][1]);
            float2 v1 = make_float2(acc[mi][nj][2], acc[mi][nj][3]);
            if (RESID) {
                float2 r0 = *(const float2*)(resid + (size_t)m * N + n);
                float2 r1 = *(const float2*)(resid + (size_t)(m + 8) * N + n);
                v0.x += r0.x; v0.y += r0.y; v1.x += r1.x; v1.y += r1.y;
            }
            *(float2*)(C + (size_t)m * N + n)       = v0;
            *(float2*)(C + (size_t)(m + 8) * N + n) = v1;
        }
    }
}

// ---------------- fp32 -> bf16 hi/lo weight convert ----------------
__global__ void k_cvt(const float* __restrict__ w, __nv_bfloat16* __restrict__ hi,
                      __nv_bfloat16* __restrict__ lo, int n)
{
    int i = blockIdx.x * blockDim.x + threadIdx.x;
    if (i < n) {
        float v = w[i];
        __nv_bfloat16 h = __float2bfloat16(v);
        hi[i] = h;
        lo[i] = __float2bfloat16(v - __bfloat162float(h));
    }
}

// ---------------- LayerNorm -> bf16 hi/lo ----------------
__global__ void k_layernorm(const float* __restrict__ x,
                            const float* __restrict__ w,
                            const float* __restrict__ b,
                            __nv_bfloat16* __restrict__ oh,
                            __nv_bfloat16* __restrict__ ol)
{
    int tok  = blockIdx.x * 8 + (threadIdx.x >> 5);
    int lane = threadIdx.x & 31;
    const float* row = x + (size_t)tok * DM;

    float4 v[4];
    float s = 0.f, s2 = 0.f;
#pragma unroll
    for (int i = 0; i < 4; i++) {
        v[i] = *(const float4*)(row + i * 128 + lane * 4);
        s  += v[i].x + v[i].y + v[i].z + v[i].w;
        s2 += v[i].x*v[i].x + v[i].y*v[i].y + v[i].z*v[i].z + v[i].w*v[i].w;
    }
#pragma unroll
    for (int o = 16; o; o >>= 1) {
        s  += __shfl_xor_sync(0xffffffffu, s,  o);
        s2 += __shfl_xor_sync(0xffffffffu, s2, o);
    }
    float mu   = s * (1.f / DM);
    float var  = s2 * (1.f / DM) - mu * mu;
    float rinv = rsqrtf(var + 1e-5f);

#pragma unroll
    for (int i = 0; i < 4; i++) {
        int d = i * 128 + lane * 4;
        float4 w4 = *(const float4*)(w + d);
        float4 b4 = *(const float4*)(b + d);
        float o4[4];
        o4[0] = (v[i].x - mu) * rinv * w4.x + b4.x;
        o4[1] = (v[i].y - mu) * rinv * w4.y + b4.y;
        o4[2] = (v[i].z - mu) * rinv * w4.z + b4.z;
        o4[3] = (v[i].w - mu) * rinv * w4.w + b4.w;
        __nv_bfloat16 hh[4], ll[4];
#pragma unroll
        for (int q = 0; q < 4; q++) {
            hh[q] = __float2bfloat16(o4[q]);
            ll[q] = __float2bfloat16(o4[q] - __bfloat162float(hh[q]));
        }
        *(uint2*)(oh + (size_t)tok * DM + d) = *(uint2*)hh;
        *(uint2*)(ol + (size_t)tok * DM + d) = *(uint2*)ll;
    }
}

// ---------------- x_proj SGEMM, both branches via blockIdx.z ----------------
#define BM 64
#define BN 64
#define BKK 16

__global__ __launch_bounds__(256)
void k_gemm2(const float* __restrict__ A0, const float* __restrict__ A1, int lda,
             const float* __restrict__ W0, const float* __restrict__ W1,
             float* __restrict__ C0, float* __restrict__ C1,
             int M, int N, int K)
{
    const float* A = blockIdx.z ? A1 : A0;
    const float* W = blockIdx.z ? W1 : W0;
    float* C = blockIdx.z ? C1 : C0;

    __shared__ __align__(16) float As[BKK][BM + 4];
    __shared__ __align__(16) float Ws[BKK][BN + 4];

    const int bm = blockIdx.y * BM;
    const int bn = blockIdx.x * BN;
    const int tid = threadIdx.x;
    const int tx = tid & 15;
    const int ty = tid >> 4;
    const int lr = tid >> 2;
    const int lq = tid & 3;

    float acc[4][4];
#pragma unroll
    for (int i = 0; i < 4; i++)
#pragma unroll
        for (int j = 0; j < 4; j++) acc[i][j] = 0.f;

    const bool wok = (bn + lr) < N;
    const float* Ap = A + (size_t)(bm + lr) * lda + lq * 4;
    const float* Wp = W + (size_t)(wok ? (bn + lr) : 0) * K + lq * 4;

    for (int k0 = 0; k0 < K; k0 += BKK) {
        float4 av = *(const float4*)(Ap + k0);
        float4 wv = wok ? *(const float4*)(Wp + k0) : make_float4(0.f, 0.f, 0.f, 0.f);
        __syncthreads();
        As[lq*4+0][lr] = av.x; As[lq*4+1][lr] = av.y;
        As[lq*4+2][lr] = av.z; As[lq*4+3][lr] = av.w;
        Ws[lq*4+0][lr] = wv.x; Ws[lq*4+1][lr] = wv.y;
        Ws[lq*4+2][lr] = wv.z; Ws[lq*4+3][lr] = wv.w;
        __syncthreads();
#pragma unroll
        for (int kk = 0; kk < BKK; kk++) {
            float4 ra = *(const float4*)(&As[kk][ty * 4]);
            float4 rw = *(const float4*)(&Ws[kk][tx * 4]);
            float a4[4] = { ra.x, ra.y, ra.z, ra.w };
            float w4[4] = { rw.x, rw.y, rw.z, rw.w };
#pragma unroll
            for (int i = 0; i < 4; i++)
#pragma unroll
                for (int j = 0; j < 4; j++)
                    acc[i][j] = fmaf(a4[i], w4[j], acc[i][j]);
        }
    }

#pragma unroll
    for (int i = 0; i < 4; i++) {
        int m = bm + ty * 4 + i;
#pragma unroll
        for (int j = 0; j < 4; j++) {
            int n = bn + tx * 4 + j;
            if (n < N) C[(size_t)m * N + n] = acc[i][j];
        }
    }
}

// ---------------- causal depthwise conv (k=2) + SiLU, fwd + reversed-bwd ------
__global__ void k_conv(const float* __restrict__ xz,
                       const float* __restrict__ cw,  const float* __restrict__ cb,
                       const float* __restrict__ cwb, const float* __restrict__ cbb,
                       float* __restrict__ xcf, float* __restrict__ xcb)
{
    int flat = blockIdx.x * blockDim.x + threadIdx.x;
    int d   = flat & (DI - 1);
    int tok = flat >> 9;
    int b   = tok >> 12;
    int s   = tok & (LSEQ - 1);

    float xcur = xz[(size_t)tok * (2 * DI) + d];
    float xprv = (s > 0) ? xz[(size_t)(tok - 1) * (2 * DI) + d] : 0.f;
    float vf = fmaf(cw[d * 2 + 0], xprv, fmaf(cw[d * 2 + 1], xcur, cb[d]));
    xcf[flat] = vf / (1.f + __expf(-vf));

    int t1 = b * LSEQ + (LSEQ - 1 - s);
    float xcb_cur = xz[(size_t)t1 * (2 * DI) + d];
    float xcb_prv = (s > 0) ? xz[(size_t)(t1 + 1) * (2 * DI) + d] : 0.f;
    float vb = fmaf(cwb[d * 2 + 0], xcb_prv, fmaf(cwb[d * 2 + 1], xcb_cur, cbb[d]));
    xcb[flat] = vb / (1.f + __expf(-vb));
}

// ---------------- zero lookback flags ----------------
__global__ void k_zero(int* __restrict__ flags) { flags[threadIdx.x] = 0; }

// ---------------- fused dt_proj + softplus + single-pass lookback scan -------
// Block = (dgroup, batch, chunk*2+branch). 128 threads, one channel d each.
// Sweep1: delta = softplus(dbc[:,:32]·Wdt[d] + b) (cached in smem), local (P,Q).
// Publish (P,Q) + release flag; lookback: backward product-accumulate h0.
// Sweep2: full recurrence from h0, emit y.
#define SCAN_SMEM (TCH*128*4 + TCH*49*4)   // delta cache + dbc cache = 90624

__global__ __launch_bounds__(128)
void k_scan(const float* __restrict__ xc0,  const float* __restrict__ xc1,
            const float* __restrict__ dbc0, const float* __restrict__ dbc1,
            const float* __restrict__ Alog0, const float* __restrict__ Alog1,
            const float* __restrict__ dtw0, const float* __restrict__ dtw1,
            const float* __restrict__ dtb0, const float* __restrict__ dtb1,
            const float* __restrict__ Dp0,  const float* __restrict__ Dp1,
            float* __restrict__ y0g, float* __restrict__ y1g,
            float* __restrict__ P0g, float* __restrict__ Q0g,
            float* __restrict__ P1g, float* __restrict__ Q1g,
            int* __restrict__ flags)
{
    extern __shared__ float sm[];
    float* delta_s = sm;                 // [TCH][128]
    float* dbc_s   = sm + TCH * 128;     // [TCH][49]

    const int t  = threadIdx.x;
    const int dg = blockIdx.x;
    const int b  = blockIdx.y;
    const int br = blockIdx.z & 1;
    const int chunk = blockIdx.z >> 1;
    const int d  = dg * 128 + t;

    const float* xc  = br ? xc1  : xc0;
    const float* dbc = br ? dbc1 : dbc0;
    const float* Alg = br ? Alog1 : Alog0;
    const float* Wdt = br ? dtw1 : dtw0;
    const float* Bdt = br ? dtb1 : dtb0;
    const float* Dpp = br ? Dp1  : Dp0;
    float* y  = br ? y1g : y0g;
    float* Pg = br ? P1g : P0g;
    float* Qg = br ? Q1g : Q0g;

    // stage Wdt rows [dg*128, +128) x32 into smem (aliases delta region), then regs
    for (int i = t; i < 128 * 32; i += 128) {
        int row = i >> 5, k = i & 31;
        sm[row * 33 + k] = Wdt[(size_t)(dg * 128) * 32 + i];
    }
    __syncthreads();
    float w[32];
#pragma unroll
    for (int k = 0; k < 32; k++) w[k] = sm[t * 33 + k];
    __syncthreads();

    // dbc rows into smem (contiguous copy, padded rows)
    const int tok0 = b * LSEQ + chunk * TCH;
    for (int i = t; i < TCH * 48; i += 128)
        dbc_s[(i / 48) * 49 + (i % 48)] = dbc[(size_t)tok0 * 48 + i];
    __syncthreads();

    float Av[DS];
    {
        float4 a0 = *(const float4*)(Alg + d * DS);
        float4 a1 = *(const float4*)(Alg + d * DS + 4);
        Av[0] = -__expf(a0.x); Av[1] = -__expf(a0.y); Av[2] = -__expf(a0.z); Av[3] = -__expf(a0.w);
        Av[4] = -__expf(a1.x); Av[5] = -__expf(a1.y); Av[6] = -__expf(a1.z); Av[7] = -__expf(a1.w);
    }
    const float bias = Bdt[d];
    const float Dd   = Dpp[d];

    // sweep 1: delta + local (P, Q)
    float h[DS], P[DS];
#pragma unroll
    for (int n = 0; n < DS; n++) { h[n] = 0.f; P[n] = 1.f; }

    for (int tt = 0; tt < TCH; tt++) {
        const float* row = &dbc_s[tt * 49];
        float a0 = bias, a1 = 0.f, a2 = 0.f, a3 = 0.f;
#pragma unroll
        for (int k = 0; k < 32; k += 4) {
            a0 = fmaf(row[k + 0], w[k + 0], a0);
            a1 = fmaf(row[k + 1], w[k + 1], a1);
            a2 = fmaf(row[k + 2], w[k + 2], a2);
            a3 = fmaf(row[k + 3], w[k + 3], a3);
        }
        float v = (a0 + a1) + (a2 + a3);
        float dl = (v > 20.f) ? v : log1pf(__expf(v));
        delta_s[tt * 128 + t] = dl;
        float u  = xc[(size_t)(tok0 + tt) * DI + d];
        float du = dl * u;
#pragma unroll
        for (int n = 0; n < DS; n++) {
            float a = __expf(dl * Av[n]);
            P[n] *= a;
            h[n] = fmaf(a, h[n], du * row[32 + n]);
        }
    }

    // publish local (P, Q) then release flag
    const int cidx = chunk * NCHAN + b * DI + d;
#pragma unroll
    for (int n = 0; n < DS; n++) {
        Pg[n * CHTOT + cidx] = P[n];
        Qg[n * CHTOT + cidx] = h[n];
    }
    __threadfence();
    __syncthreads();
    if (t == 0) {
        int fi = blockIdx.z * 16 + b * 4 + dg;
        asm volatile("st.global.release.gpu.b32 [%0], %1;" :: "l"(flags + fi), "r"(1) : "memory");
    }

    // lookback: h0 = sum_j Q_j * prod_{k>j} P_k  (j = chunk-1 .. 0)
    float h0[DS], pref[DS];
#pragma unroll
    for (int n = 0; n < DS; n++) { h0[n] = 0.f; pref[n] = 1.f; }
    for (int j = chunk - 1; j >= 0; j--) {
        const int fj = (j * 2 + br) * 16 + b * 4 + dg;
        int f;
        do {
            asm volatile("ld.global.acquire.gpu.b32 %0, [%1];" : "=r"(f) : "l"(flags + fj) : "memory");
            if (!f) __nanosleep(64);
        } while (!f);
        const int idxj = j * NCHAN + b * DI + d;
#pragma unroll
        for (int n = 0; n < DS; n++) {
            h0[n] = fmaf(pref[n], Qg[n * CHTOT + idxj], h0[n]);
            pref[n] *= Pg[n * CHTOT + idxj];
        }
    }

    // sweep 2: full recurrence from h0, emit y
#pragma unroll
    for (int n = 0; n < DS; n++) h[n] = h0[n];
    for (int tt = 0; tt < TCH; tt++) {
        float dl = delta_s[tt * 128 + t];
        float u  = xc[(size_t)(tok0 + tt) * DI + d];
        float du = dl * u;
        const float* row = &dbc_s[tt * 49];
        float yv = 0.f;
#pragma unroll
        for (int n = 0; n < DS; n++) {
            float a = __expf(dl * Av[n]);
            h[n] = fmaf(a, h[n], du * row[32 + n]);
            yv = fmaf(h[n], row[40 + n], yv);
        }
        y[(size_t)(tok0 + tt) * DI + d] = fmaf(u, Dd, yv);
    }
}

// ---------------- combine branches, gate, RMSNorm -> bf16 hi/lo ---------------
__global__ void k_rms(const float* __restrict__ yf, const float* __restrict__ yb,
                      const float* __restrict__ xz, const float* __restrict__ rw,
                      __nv_bfloat16* __restrict__ oh, __nv_bfloat16* __restrict__ ol)
{
    int tok  = blockIdx.x * 8 + (threadIdx.x >> 5);
    int lane = threadIdx.x & 31;
    int s    = tok & (LSEQ - 1);
    int rtok = tok - s + (LSEQ - 1 - s);

    float4 v[4];
    float ss = 0.f;
#pragma unroll
    for (int i = 0; i < 4; i++) {
        int d = i * 128 + lane * 4;
        float4 a = *(const float4*)(yf + (size_t)tok * DI + d);
        float4 c = *(const float4*)(yb + (size_t)rtok * DI + d);
        float4 z = *(const float4*)(xz + (size_t)tok * (2 * DI) + DI + d);
        float4 o;
        o.x = 0.5f * (a.x + c.x) * (z.x / (1.f + __expf(-z.x)));
        o.y = 0.5f * (a.y + c.y) * (z.y / (1.f + __expf(-z.y)));
        o.z = 0.5f * (a.z + c.z) * (z.z / (1.f + __expf(-z.z)));
        o.w = 0.5f * (a.w + c.w) * (z.w / (1.f + __expf(-z.w)));
        ss += o.x*o.x + o.y*o.y + o.z*o.z + o.w*o.w;
        v[i] = o;
    }
#pragma unroll
    for (int o = 16; o; o >>= 1) ss += __shfl_xor_sync(0xffffffffu, ss, o);
    float sc = rsqrtf(ss * (1.f / DI) + 1e-5f);

#pragma unroll
    for (int i = 0; i < 4; i++) {
        int d = i * 128 + lane * 4;
        float4 w4 = *(const float4*)(rw + d);
        float o4[4];
        o4[0] = v[i].x * sc * w4.x;
        o4[1] = v[i].y * sc * w4.y;
        o4[2] = v[i].z * sc * w4.z;
        o4[3] = v[i].w * sc * w4.w;
        __nv_bfloat16 hh[4], ll[4];
#pragma unroll
        for (int q = 0; q < 4; q++) {
            hh[q] = __float2bfloat16(o4[q]);
            ll[q] = __float2bfloat16(o4[q] - __bfloat162float(hh[q]));
        }
        *(uint2*)(oh + (size_t)tok * DI + d) = *(uint2*)hh;
        *(uint2*)(ol + (size_t)tok * DI + d) = *(uint2*)ll;
    }
}

// ---------------- host launch ----------------
extern "C" void kernel_launch(void* const* d_in, const int* in_sizes, int n_in,
                              void* d_out, int out_size)
{
    const float* x          = (const float*)d_in[0];
    const float* ln_w       = (const float*)d_in[1];
    const float* ln_b       = (const float*)d_in[2];
    const float* in_proj_w  = (const float*)d_in[3];
    const float* conv_w     = (const float*)d_in[4];
    const float* conv_b     = (const float*)d_in[5];
    const float* x_proj_w   = (const float*)d_in[6];
    const float* dt_proj_w  = (const float*)d_in[7];
    const float* dt_proj_b  = (const float*)d_in[8];
    const float* A_log      = (const float*)d_in[9];
    const float* Dp         = (const float*)d_in[10];
    const float* conv_w_b   = (const float*)d_in[11];
    const float* conv_b_b   = (const float*)d_in[12];
    const float* x_proj_w_b = (const float*)d_in[13];
    const float* dt_proj_w_b= (const float*)d_in[14];
    const float* dt_proj_b_b= (const float*)d_in[15];
    const float* A_log_b    = (const float*)d_in[16];
    const float* D_b        = (const float*)d_in[17];
    const float* rms_w      = (const float*)d_in[18];
    const float* out_proj_w = (const float*)d_in[19];
    float* out = (float*)d_out;

    __nv_bfloat16 *lnh, *lnl, *wih, *wil, *woh, *wol, *ynh, *ynl;
    float *xz, *xc0, *xc1, *dbc0, *dbc1, *y0, *y1;
    float *P0, *Q0, *P1, *Q1;
    int* flags;
    cudaGetSymbolAddress((void**)&lnh,  g_lnh);
    cudaGetSymbolAddress((void**)&lnl,  g_lnl);
    cudaGetSymbolAddress((void**)&wih,  g_wih);
    cudaGetSymbolAddress((void**)&wil,  g_wil);
    cudaGetSymbolAddress((void**)&woh,  g_woh);
    cudaGetSymbolAddress((void**)&wol,  g_wol);
    cudaGetSymbolAddress((void**)&ynh,  g_ynh);
    cudaGetSymbolAddress((void**)&ynl,  g_ynl);
    cudaGetSymbolAddress((void**)&xz,   g_xz);
    cudaGetSymbolAddress((void**)&xc0,  g_xc0);
    cudaGetSymbolAddress((void**)&xc1,  g_xc1);
    cudaGetSymbolAddress((void**)&dbc0, g_dbc0);
    cudaGetSymbolAddress((void**)&dbc1, g_dbc1);
    cudaGetSymbolAddress((void**)&y0,   g_y0);
    cudaGetSymbolAddress((void**)&y1,   g_y1);
    cudaGetSymbolAddress((void**)&P0,   g_P0);
    cudaGetSymbolAddress((void**)&Q0,   g_Q0);
    cudaGetSymbolAddress((void**)&P1,   g_P1);
    cudaGetSymbolAddress((void**)&Q1,   g_Q1);
    cudaGetSymbolAddress((void**)&flags, g_flags);

    cudaFuncSetAttribute(k_mma<false>, cudaFuncAttributeMaxDynamicSharedMemorySize, MMA_SMEM);
    cudaFuncSetAttribute(k_mma<true>,  cudaFuncAttributeMaxDynamicSharedMemorySize, MMA_SMEM);
    cudaFuncSetAttribute(k_scan, cudaFuncAttributeMaxDynamicSharedMemorySize, SCAN_SMEM);

    // 0. convert weights to bf16 hi/lo
    k_cvt<<<(2*DI*DM + 255)/256, 256>>>(in_proj_w,  wih, wil, 2*DI*DM);
    k_cvt<<<(DM*DI   + 255)/256, 256>>>(out_proj_w, woh, wol, DM*DI);

    // 1. LayerNorm -> bf16 hi/lo
    k_layernorm<<<NTOK / 8, 256>>>(x, ln_w, ln_b, lnh, lnl);

    // 2. in_proj (mma.sync split-bf16): (16384,512) x (1024,512)^T -> xz fp32
    k_mma<false><<<dim3(2*DI/128, NTOK/128), 256, MMA_SMEM>>>(lnh, lnl, wih, wil, xz, 2*DI, nullptr);

    // 3. conv + silu (fwd and reversed-bwd)
    k_conv<<<(NTOK * DI) / 256, 256>>>(xz, conv_w, conv_b, conv_w_b, conv_b_b, xc0, xc1);

    // 4. x_proj both branches: (16384,512) x (48,512)^T -> dbc (16384,48)
    k_gemm2<<<dim3(1, NTOK/BM, 2), 256>>>(
        xc0, xc1, DI, x_proj_w, x_proj_w_b, dbc0, dbc1, NTOK, DBCW, DI);

    // 5. fused dt_proj + selective scan (single pass, decoupled lookback)
    k_zero<<<1, 1024>>>(flags);
    k_scan<<<dim3(DI/128, BATCH, NCH*2), 128, SCAN_SMEM>>>(
        xc0, xc1, dbc0, dbc1, A_log, A_log_b,
        dt_proj_w, dt_proj_w_b, dt_proj_b, dt_proj_b_b,
        Dp, D_b, y0, y1, P0, Q0, P1, Q1, flags);

    // 6. combine + silu(z) gate + RMSNorm -> bf16 hi/lo
    k_rms<<<NTOK / 8, 256>>>(y0, y1, xz, rms_w, ynh, ynl);

    // 7. out_proj (mma.sync split-bf16) + residual -> d_out
    k_mma<true><<<dim3(DM/128, NTOK/128), 256, MMA_SMEM>>>(ynh, ynl, woh, wol, out, DM, x);
}

// round 5
// speedup vs baseline: 1.9911x; 1.1626x over previous
#include <cuda_runtime.h>
#include <cuda_bf16.h>
#include <cstdint>

// ---------------- problem constants ----------------
#define BATCH   4
#define LSEQ    4096
#define NTOK    (BATCH*LSEQ)       // 16384
#define DM      512
#define DI      512
#define DS      8
#define DTRANK  32
#define DBCW    48                 // DT_RANK + 2*D_STATE

// chunked scan config
#define NCH     64
#define TCH     (LSEQ/NCH)         // 64
#define NCHAN   (BATCH*DI)         // 2048
#define CHTOT   (NCHAN*NCH)        // 131072

// ---------------- scratch (device globals; no runtime alloc) ----------------
__device__ __nv_bfloat16 g_lnh[NTOK*DM];
__device__ __nv_bfloat16 g_lnl[NTOK*DM];
__device__ __nv_bfloat16 g_wih[2*DI*DM];
__device__ __nv_bfloat16 g_wil[2*DI*DM];
__device__ __nv_bfloat16 g_woh[DM*DI];
__device__ __nv_bfloat16 g_wol[DM*DI];
__device__ __nv_bfloat16 g_ynh[NTOK*DI];
__device__ __nv_bfloat16 g_ynl[NTOK*DI];
__device__ float g_xz  [NTOK*2*DI];
__device__ float g_xc0 [NTOK*DI];
__device__ float g_xc1 [NTOK*DI];
__device__ float g_dbc0[NTOK*DBCW];
__device__ float g_dbc1[NTOK*DBCW];
__device__ float g_y0  [NTOK*DI];
__device__ float g_y1  [NTOK*DI];
__device__ float g_P0  [DS*CHTOT];
__device__ float g_Q0  [DS*CHTOT];
__device__ float g_P1  [DS*CHTOT];
__device__ float g_Q1  [DS*CHTOT];
__device__ int   g_flags[2048];

// ---------------- helpers ----------------
__device__ __forceinline__ uint32_t smem_u32(const void* p) {
    uint32_t a;
    asm("{ .reg .u64 t; cvta.to.shared.u64 t, %1; cvt.u32.u64 %0, t; }" : "=r"(a) : "l"(p));
    return a;
}
__device__ __forceinline__ void ldsm4(uint32_t* r, uint32_t addr) {
    asm volatile("ldmatrix.sync.aligned.m8n8.x4.shared.b16 {%0,%1,%2,%3}, [%4];"
        : "=r"(r[0]), "=r"(r[1]), "=r"(r[2]), "=r"(r[3]) : "r"(addr));
}
__device__ __forceinline__ void mma16816(float* c, const uint32_t* a, const uint32_t* b) {
    asm volatile("mma.sync.aligned.m16n8k16.row.col.f32.bf16.bf16.f32 "
        "{%0,%1,%2,%3},{%4,%5,%6,%7},{%8,%9},{%0,%1,%2,%3};"
        : "+f"(c[0]), "+f"(c[1]), "+f"(c[2]), "+f"(c[3])
        : "r"(a[0]), "r"(a[1]), "r"(a[2]), "r"(a[3]), "r"(b[0]), "r"(b[1]));
}

// ---------------- mma.sync split-bf16 GEMM, 3-stage pipeline ----------------
#define KCH     64
#define NKCH    (512/KCH)          // 8
#define TILEB   16384              // one 128x64 bf16 tile in smem
#define STG_SZ  (4*TILEB)          // Ah, Al, Bh, Bl = 65536
#define MMA_SMEM (3*STG_SZ)        // 196608

__device__ __forceinline__ void mma_load_chunk(
    const __nv_bfloat16* __restrict__ Ah, const __nv_bfloat16* __restrict__ Al,
    const __nv_bfloat16* __restrict__ Bh, const __nv_bfloat16* __restrict__ Bl,
    int m0, int n0, int kc, uint32_t stage)
{
    const int t = threadIdx.x;
#pragma unroll
    for (int it = 0; it < 16; it++) {
        int idx   = it * 256 + t;
        int tile  = idx >> 10;             // 0:Ah 1:Al 2:Bh 3:Bl
        int local = idx & 1023;
        int row   = local >> 3;
        int c     = local & 7;
        const __nv_bfloat16* gb = (tile == 0) ? Ah : (tile == 1) ? Al : (tile == 2) ? Bh : Bl;
        int base = (tile < 2) ? m0 : n0;
        const void* ga = gb + (size_t)(base + row) * 512 + kc * KCH + c * 8;
        uint32_t sa = stage + tile * TILEB + row * 128 + ((c ^ (row & 7)) << 4);
        asm volatile("cp.async.cg.shared.global [%0], [%1], 16;" :: "r"(sa), "l"(ga));
    }
}

template<bool RESID>
__global__ __launch_bounds__(256)
void k_mma(const __nv_bfloat16* __restrict__ Ah, const __nv_bfloat16* __restrict__ Al,
           const __nv_bfloat16* __restrict__ Bh, const __nv_bfloat16* __restrict__ Bl,
           float* __restrict__ C, int N, const float* __restrict__ resid)
{
    extern __shared__ __align__(128) char smem[];
    const uint32_t sb = smem_u32(smem);
    const int m0 = blockIdx.y * 128;
    const int n0 = blockIdx.x * 128;
    const int w  = threadIdx.x >> 5;
    const int lane = threadIdx.x & 31;
    const int wm = (w >> 2) * 64;
    const int wn = (w & 3) * 32;

    float acc[4][4][4];
#pragma unroll
    for (int i = 0; i < 4; i++)
#pragma unroll
        for (int j = 0; j < 4; j++)
#pragma unroll
            for (int q = 0; q < 4; q++) acc[i][j][q] = 0.f;

    const int ar  = lane & 15;
    const int ach = lane >> 4;
    const int bt8 = lane & 7;
    const int bg  = lane >> 3;
    const int bn8 = (bg >> 1) << 3;
    const int bch = bg & 1;

    mma_load_chunk(Ah, Al, Bh, Bl, m0, n0, 0, sb);
    asm volatile("cp.async.commit_group;");
    mma_load_chunk(Ah, Al, Bh, Bl, m0, n0, 1, sb + STG_SZ);
    asm volatile("cp.async.commit_group;");

    for (int i = 0; i < NKCH; i++) {
        if (i < NKCH - 1) asm volatile("cp.async.wait_group 1;");
        else              asm volatile("cp.async.wait_group 0;");
        __syncthreads();

        // issue next loads BEFORE compute (into stage consumed at iter i-1)
        if (i < NKCH - 2) {
            mma_load_chunk(Ah, Al, Bh, Bl, m0, n0, i + 2, sb + ((i + 2) % 3) * STG_SZ);
            asm volatile("cp.async.commit_group;");
        }

        const uint32_t stg = sb + (i % 3) * STG_SZ;
        const uint32_t sAh = stg, sAl = stg + TILEB, sBh = stg + 2*TILEB, sBl = stg + 3*TILEB;

#pragma unroll
        for (int ks = 0; ks < 4; ks++) {
            uint32_t ah[4][4], al[4][4], bh[2][4], bl[2][4];
#pragma unroll
            for (int mi = 0; mi < 4; mi++) {
                int r = wm + mi * 16 + ar;
                int c = ks * 2 + ach;
                uint32_t off = r * 128 + (((uint32_t)(c ^ (r & 7))) << 4);
                ldsm4(ah[mi], sAh + off);
                ldsm4(al[mi], sAl + off);
            }
#pragma unroll
            for (int ni = 0; ni < 2; ni++) {
                int n = wn + ni * 16 + bn8 + bt8;
                int c = ks * 2 + bch;
                uint32_t off = n * 128 + (((uint32_t)(c ^ (n & 7))) << 4);
                ldsm4(bh[ni], sBh + off);
                ldsm4(bl[ni], sBl + off);
            }
#pragma unroll
            for (int mi = 0; mi < 4; mi++)
#pragma unroll
                for (int nj = 0; nj < 4; nj++) {
                    const uint32_t* bhp = &bh[nj >> 1][(nj & 1) * 2];
                    const uint32_t* blp = &bl[nj >> 1][(nj & 1) * 2];
                    mma16816(acc[mi][nj], ah[mi], bhp);
                    mma16816(acc[mi][nj], ah[mi], blp);
                    mma16816(acc[mi][nj], al[mi], bhp);
                }
        }
    }

#pragma unroll
    for (int mi = 0; mi < 4; mi++) {
        int m = m0 + wm + mi * 16 + (lane >> 2);
#pragma unroll
        for (int nj = 0; nj < 4; nj++) {
            int n = n0 + wn + nj * 8 + ((lane & 3) << 1);
            float2 v0 = make_float2(acc[mi][nj][0], acc[mi][nj][1]);
            float2 v1 = make_float2(acc[mi][nj][2], acc[mi][nj][3]);
            if (RESID) {
                float2 r0 = *(const float2*)(resid + (size_t)m * N + n);
                float2 r1 = *(const float2*)(resid + (size_t)(m + 8) * N + n);
                v0.x += r0.x; v0.y += r0.y; v1.x += r1.x; v1.y += r1.y;
            }
            *(float2*)(C + (size_t)m * N + n)       = v0;
            *(float2*)(C + (size_t)(m + 8) * N + n) = v1;
        }
    }
}

// ---------------- fp32 -> bf16 hi/lo weight convert ----------------
__global__ void k_cvt(const float* __restrict__ w, __nv_bfloat16* __restrict__ hi,
                      __nv_bfloat16* __restrict__ lo, int n)
{
    int i = blockIdx.x * blockDim.x + threadIdx.x;
    if (i < n) {
        float v = w[i];
        __nv_bfloat16 h = __float2bfloat16(v);
        hi[i] = h;
        lo[i] = __float2bfloat16(v - __bfloat162float(h));
    }
}

// ---------------- LayerNorm -> bf16 hi/lo ----------------
__global__ void k_layernorm(const float* __restrict__ x,
                            const float* __restrict__ w,
                            const float* __restrict__ b,
                            __nv_bfloat16* __restrict__ oh,
                            __nv_bfloat16* __restrict__ ol)
{
    int tok  = blockIdx.x * 8 + (threadIdx.x >> 5);
    int lane = threadIdx.x & 31;
    const float* row = x + (size_t)tok * DM;

    float4 v[4];
    float s = 0.f, s2 = 0.f;
#pragma unroll
    for (int i = 0; i < 4; i++) {
        v[i] = *(const float4*)(row + i * 128 + lane * 4);
        s  += v[i].x + v[i].y + v[i].z + v[i].w;
        s2 += v[i].x*v[i].x + v[i].y*v[i].y + v[i].z*v[i].z + v[i].w*v[i].w;
    }
#pragma unroll
    for (int o = 16; o; o >>= 1) {
        s  += __shfl_xor_sync(0xffffffffu, s,  o);
        s2 += __shfl_xor_sync(0xffffffffu, s2, o);
    }
    float mu   = s * (1.f / DM);
    float var  = s2 * (1.f / DM) - mu * mu;
    float rinv = rsqrtf(var + 1e-5f);

#pragma unroll
    for (int i = 0; i < 4; i++) {
        int d = i * 128 + lane * 4;
        float4 w4 = *(const float4*)(w + d);
        float4 b4 = *(const float4*)(b + d);
        float o4[4];
        o4[0] = (v[i].x - mu) * rinv * w4.x + b4.x;
        o4[1] = (v[i].y - mu) * rinv * w4.y + b4.y;
        o4[2] = (v[i].z - mu) * rinv * w4.z + b4.z;
        o4[3] = (v[i].w - mu) * rinv * w4.w + b4.w;
        __nv_bfloat16 hh[4], ll[4];
#pragma unroll
        for (int q = 0; q < 4; q++) {
            hh[q] = __float2bfloat16(o4[q]);
            ll[q] = __float2bfloat16(o4[q] - __bfloat162float(hh[q]));
        }
        *(uint2*)(oh + (size_t)tok * DM + d) = *(uint2*)hh;
        *(uint2*)(ol + (size_t)tok * DM + d) = *(uint2*)ll;
    }
}

// ---------------- x_proj SGEMM, both branches via blockIdx.z ----------------
#define BM 64
#define BN 64
#define BKK 16

__global__ __launch_bounds__(256)
void k_gemm2(const float* __restrict__ A0, const float* __restrict__ A1, int lda,
             const float* __restrict__ W0, const float* __restrict__ W1,
             float* __restrict__ C0, float* __restrict__ C1,
             int M, int N, int K)
{
    const float* A = blockIdx.z ? A1 : A0;
    const float* W = blockIdx.z ? W1 : W0;
    float* C = blockIdx.z ? C1 : C0;

    __shared__ __align__(16) float As[BKK][BM + 4];
    __shared__ __align__(16) float Ws[BKK][BN + 4];

    const int bm = blockIdx.y * BM;
    const int bn = blockIdx.x * BN;
    const int tid = threadIdx.x;
    const int tx = tid & 15;
    const int ty = tid >> 4;
    const int lr = tid >> 2;
    const int lq = tid & 3;

    float acc[4][4];
#pragma unroll
    for (int i = 0; i < 4; i++)
#pragma unroll
        for (int j = 0; j < 4; j++) acc[i][j] = 0.f;

    const bool wok = (bn + lr) < N;
    const float* Ap = A + (size_t)(bm + lr) * lda + lq * 4;
    const float* Wp = W + (size_t)(wok ? (bn + lr) : 0) * K + lq * 4;

    for (int k0 = 0; k0 < K; k0 += BKK) {
        float4 av = *(const float4*)(Ap + k0);
        float4 wv = wok ? *(const float4*)(Wp + k0) : make_float4(0.f, 0.f, 0.f, 0.f);
        __syncthreads();
        As[lq*4+0][lr] = av.x; As[lq*4+1][lr] = av.y;
        As[lq*4+2][lr] = av.z; As[lq*4+3][lr] = av.w;
        Ws[lq*4+0][lr] = wv.x; Ws[lq*4+1][lr] = wv.y;
        Ws[lq*4+2][lr] = wv.z; Ws[lq*4+3][lr] = wv.w;
        __syncthreads();
#pragma unroll
        for (int kk = 0; kk < BKK; kk++) {
            float4 ra = *(const float4*)(&As[kk][ty * 4]);
            float4 rw = *(const float4*)(&Ws[kk][tx * 4]);
            float a4[4] = { ra.x, ra.y, ra.z, ra.w };
            float w4[4] = { rw.x, rw.y, rw.z, rw.w };
#pragma unroll
            for (int i = 0; i < 4; i++)
#pragma unroll
                for (int j = 0; j < 4; j++)
                    acc[i][j] = fmaf(a4[i], w4[j], acc[i][j]);
        }
    }

#pragma unroll
    for (int i = 0; i < 4; i++) {
        int m = bm + ty * 4 + i;
#pragma unroll
        for (int j = 0; j < 4; j++) {
            int n = bn + tx * 4 + j;
            if (n < N) C[(size_t)m * N + n] = acc[i][j];
        }
    }
}

// ---------------- causal depthwise conv (k=2) + SiLU, fwd + reversed-bwd ------
__global__ void k_conv(const float* __restrict__ xz,
                       const float* __restrict__ cw,  const float* __restrict__ cb,
                       const float* __restrict__ cwb, const float* __restrict__ cbb,
                       float* __restrict__ xcf, float* __restrict__ xcb)
{
    int flat = blockIdx.x * blockDim.x + threadIdx.x;
    int d   = flat & (DI - 1);
    int tok = flat >> 9;
    int b   = tok >> 12;
    int s   = tok & (LSEQ - 1);

    float xcur = xz[(size_t)tok * (2 * DI) + d];
    float xprv = (s > 0) ? xz[(size_t)(tok - 1) * (2 * DI) + d] : 0.f;
    float vf = fmaf(cw[d * 2 + 0], xprv, fmaf(cw[d * 2 + 1], xcur, cb[d]));
    xcf[flat] = vf / (1.f + __expf(-vf));

    int t1 = b * LSEQ + (LSEQ - 1 - s);
    float xcb_cur = xz[(size_t)t1 * (2 * DI) + d];
    float xcb_prv = (s > 0) ? xz[(size_t)(t1 + 1) * (2 * DI) + d] : 0.f;
    float vb = fmaf(cwb[d * 2 + 0], xcb_prv, fmaf(cwb[d * 2 + 1], xcb_cur, cbb[d]));
    xcb[flat] = vb / (1.f + __expf(-vb));
}

// ---------------- zero lookback flags ----------------
__global__ void k_zero(int* __restrict__ flags) {
    flags[blockIdx.x * 1024 + threadIdx.x] = 0;
}

// ---------------- fused dt_proj + softplus + single-pass lookback scan -------
// A_log = log(1..8) tiled (setup_inputs) => A[n] = (n+1)*A[0]; fast path uses
// one exp + power chain per step (runtime-verified; generic fallback kept).
#define SCAN_SMEM (TCH*128*4 + TCH*49*4)   // 32768 + 12544 = 45312

__global__ __launch_bounds__(128)
void k_scan(const float* __restrict__ xc0,  const float* __restrict__ xc1,
            const float* __restrict__ dbc0, const float* __restrict__ dbc1,
            const float* __restrict__ Alog0, const float* __restrict__ Alog1,
            const float* __restrict__ dtw0, const float* __restrict__ dtw1,
            const float* __restrict__ dtb0, const float* __restrict__ dtb1,
            const float* __restrict__ Dp0,  const float* __restrict__ Dp1,
            float* __restrict__ y0g, float* __restrict__ y1g,
            float* __restrict__ P0g, float* __restrict__ Q0g,
            float* __restrict__ P1g, float* __restrict__ Q1g,
            int* __restrict__ flags)
{
    extern __shared__ float sm[];
    float* delta_s = sm;                 // [TCH][128]
    float* dbc_s   = sm + TCH * 128;     // [TCH][49]

    const int t  = threadIdx.x;
    const int dg = blockIdx.x;
    const int b  = blockIdx.y;
    const int br = blockIdx.z & 1;
    const int chunk = blockIdx.z >> 1;
    const int d  = dg * 128 + t;

    const float* xc  = br ? xc1  : xc0;
    const float* dbc = br ? dbc1 : dbc0;
    const float* Alg = br ? Alog1 : Alog0;
    const float* Wdt = br ? dtw1 : dtw0;
    const float* Bdt = br ? dtb1 : dtb0;
    const float* Dpp = br ? Dp1  : Dp0;
    float* y  = br ? y1g : y0g;
    float* Pg = br ? P1g : P0g;
    float* Qg = br ? Q1g : Q0g;

    // stage Wdt rows into smem (aliases delta region), then regs
    for (int i = t; i < 128 * 32; i += 128) {
        int row = i >> 5, k = i & 31;
        sm[row * 33 + k] = Wdt[(size_t)(dg * 128) * 32 + i];
    }
    const int tok0 = b * LSEQ + chunk * TCH;
    for (int i = t; i < TCH * 48; i += 128)
        dbc_s[(i / 48) * 49 + (i % 48)] = dbc[(size_t)tok0 * 48 + i];
    __syncthreads();
    float w[32];
#pragma unroll
    for (int k = 0; k < 32; k++) w[k] = sm[t * 33 + k];
    __syncthreads();

    float Av[DS];
    {
        float4 a0 = *(const float4*)(Alg + d * DS);
        float4 a1 = *(const float4*)(Alg + d * DS + 4);
        Av[0] = -__expf(a0.x); Av[1] = -__expf(a0.y); Av[2] = -__expf(a0.z); Av[3] = -__expf(a0.w);
        Av[4] = -__expf(a1.x); Av[5] = -__expf(a1.y); Av[6] = -__expf(a1.z); Av[7] = -__expf(a1.w);
    }
    const float Av0 = Av[0];
    bool uni = true;
#pragma unroll
    for (int n = 1; n < DS; n++)
        uni = uni && (fabsf(Av[n] - (n + 1) * Av0) <= 2e-5f * (n + 1));

    const float bias = Bdt[d];
    const float Dd   = Dpp[d];

    // sweep 1: delta + local (P, Q)
    float h[DS], P[DS], S = 0.f;
#pragma unroll
    for (int n = 0; n < DS; n++) { h[n] = 0.f; P[n] = 1.f; }

    for (int tt = 0; tt < TCH; tt++) {
        const float* row = &dbc_s[tt * 49];
        float a0 = bias, a1 = 0.f, a2 = 0.f, a3 = 0.f;
#pragma unroll
        for (int k = 0; k < 32; k += 4) {
            a0 = fmaf(row[k + 0], w[k + 0], a0);
            a1 = fmaf(row[k + 1], w[k + 1], a1);
            a2 = fmaf(row[k + 2], w[k + 2], a2);
            a3 = fmaf(row[k + 3], w[k + 3], a3);
        }
        float v = (a0 + a1) + (a2 + a3);
        float dl = (v > 20.f) ? v : log1pf(__expf(v));
        delta_s[tt * 128 + t] = dl;
        float u  = xc[(size_t)(tok0 + tt) * DI + d];
        float du = dl * u;
        if (uni) {
            S += dl;
            float e1 = __expf(dl * Av0);
            float an = 1.f;
#pragma unroll
            for (int n = 0; n < DS; n++) {
                an *= e1;
                h[n] = fmaf(an, h[n], du * row[32 + n]);
            }
        } else {
#pragma unroll
            for (int n = 0; n < DS; n++) {
                float a = __expf(dl * Av[n]);
                P[n] *= a;
                h[n] = fmaf(a, h[n], du * row[32 + n]);
            }
        }
    }
    if (uni) {
#pragma unroll
        for (int n = 0; n < DS; n++) P[n] = __expf(S * Av[n]);
    }

    // publish local (P, Q) then release flag
    const int cidx = chunk * NCHAN + b * DI + d;
#pragma unroll
    for (int n = 0; n < DS; n++) {
        Pg[n * CHTOT + cidx] = P[n];
        Qg[n * CHTOT + cidx] = h[n];
    }
    __threadfence();
    __syncthreads();
    if (t == 0) {
        int fi = blockIdx.z * 16 + b * 4 + dg;
        asm volatile("st.global.release.gpu.b32 [%0], %1;" :: "l"(flags + fi), "r"(1) : "memory");
    }

    // lookback: h0 = sum_j Q_j * prod_{k>j} P_k  (j = chunk-1 .. 0)
    float h0[DS], pref[DS];
#pragma unroll
    for (int n = 0; n < DS; n++) { h0[n] = 0.f; pref[n] = 1.f; }
    for (int j = chunk - 1; j >= 0; j--) {
        const int fj = (j * 2 + br) * 16 + b * 4 + dg;
        int f;
        do {
            asm volatile("ld.global.acquire.gpu.b32 %0, [%1];" : "=r"(f) : "l"(flags + fj) : "memory");
            if (!f) __nanosleep(64);
        } while (!f);
        const int idxj = j * NCHAN + b * DI + d;
#pragma unroll
        for (int n = 0; n < DS; n++) {
            h0[n] = fmaf(pref[n], Qg[n * CHTOT + idxj], h0[n]);
            pref[n] *= Pg[n * CHTOT + idxj];
        }
    }

    // sweep 2: full recurrence from h0, emit y
#pragma unroll
    for (int n = 0; n < DS; n++) h[n] = h0[n];
    for (int tt = 0; tt < TCH; tt++) {
        float dl = delta_s[tt * 128 + t];
        float u  = xc[(size_t)(tok0 + tt) * DI + d];
        float du = dl * u;
        const float* row = &dbc_s[tt * 49];
        float yv = 0.f;
        if (uni) {
            float e1 = __expf(dl * Av0);
            float an = 1.f;
#pragma unroll
            for (int n = 0; n < DS; n++) {
                an *= e1;
                h[n] = fmaf(an, h[n], du * row[32 + n]);
                yv = fmaf(h[n], row[40 + n], yv);
            }
        } else {
#pragma unroll
            for (int n = 0; n < DS; n++) {
                float a = __expf(dl * Av[n]);
                h[n] = fmaf(a, h[n], du * row[32 + n]);
                yv = fmaf(h[n], row[40 + n], yv);
            }
        }
        y[(size_t)(tok0 + tt) * DI + d] = fmaf(u, Dd, yv);
    }
}

// ---------------- combine branches, gate, RMSNorm -> bf16 hi/lo ---------------
__global__ void k_rms(const float* __restrict__ yf, const float* __restrict__ yb,
                      const float* __restrict__ xz, const float* __restrict__ rw,
                      __nv_bfloat16* __restrict__ oh, __nv_bfloat16* __restrict__ ol)
{
    int tok  = blockIdx.x * 8 + (threadIdx.x >> 5);
    int lane = threadIdx.x & 31;
    int s    = tok & (LSEQ - 1);
    int rtok = tok - s + (LSEQ - 1 - s);

    float4 v[4];
    float ss = 0.f;
#pragma unroll
    for (int i = 0; i < 4; i++) {
        int d = i * 128 + lane * 4;
        float4 a = *(const float4*)(yf + (size_t)tok * DI + d);
        float4 c = *(const float4*)(yb + (size_t)rtok * DI + d);
        float4 z = *(const float4*)(xz + (size_t)tok * (2 * DI) + DI + d);
        float4 o;
        o.x = 0.5f * (a.x + c.x) * (z.x / (1.f + __expf(-z.x)));
        o.y = 0.5f * (a.y + c.y) * (z.y / (1.f + __expf(-z.y)));
        o.z = 0.5f * (a.z + c.z) * (z.z / (1.f + __expf(-z.z)));
        o.w = 0.5f * (a.w + c.w) * (z.w / (1.f + __expf(-z.w)));
        ss += o.x*o.x + o.y*o.y + o.z*o.z + o.w*o.w;
        v[i] = o;
    }
#pragma unroll
    for (int o = 16; o; o >>= 1) ss += __shfl_xor_sync(0xffffffffu, ss, o);
    float sc = rsqrtf(ss * (1.f / DI) + 1e-5f);

#pragma unroll
    for (int i = 0; i < 4; i++) {
        int d = i * 128 + lane * 4;
        float4 w4 = *(const float4*)(rw + d);
        float o4[4];
        o4[0] = v[i].x * sc * w4.x;
        o4[1] = v[i].y * sc * w4.y;
        o4[2] = v[i].z * sc * w4.z;
        o4[3] = v[i].w * sc * w4.w;
        __nv_bfloat16 hh[4], ll[4];
#pragma unroll
        for (int q = 0; q < 4; q++) {
            hh[q] = __float2bfloat16(o4[q]);
            ll[q] = __float2bfloat16(o4[q] - __bfloat162float(hh[q]));
        }
        *(uint2*)(oh + (size_t)tok * DI + d) = *(uint2*)hh;
        *(uint2*)(ol + (size_t)tok * DI + d) = *(uint2*)ll;
    }
}

// ---------------- host launch ----------------
extern "C" void kernel_launch(void* const* d_in, const int* in_sizes, int n_in,
                              void* d_out, int out_size)
{
    const float* x          = (const float*)d_in[0];
    const float* ln_w       = (const float*)d_in[1];
    const float* ln_b       = (const float*)d_in[2];
    const float* in_proj_w  = (const float*)d_in[3];
    const float* conv_w     = (const float*)d_in[4];
    const float* conv_b     = (const float*)d_in[5];
    const float* x_proj_w   = (const float*)d_in[6];
    const float* dt_proj_w  = (const float*)d_in[7];
    const float* dt_proj_b  = (const float*)d_in[8];
    const float* A_log      = (const float*)d_in[9];
    const float* Dp         = (const float*)d_in[10];
    const float* conv_w_b   = (const float*)d_in[11];
    const float* conv_b_b   = (const float*)d_in[12];
    const float* x_proj_w_b = (const float*)d_in[13];
    const float* dt_proj_w_b= (const float*)d_in[14];
    const float* dt_proj_b_b= (const float*)d_in[15];
    const float* A_log_b    = (const float*)d_in[16];
    const float* D_b        = (const float*)d_in[17];
    const float* rms_w      = (const float*)d_in[18];
    const float* out_proj_w = (const float*)d_in[19];
    float* out = (float*)d_out;

    __nv_bfloat16 *lnh, *lnl, *wih, *wil, *woh, *wol, *ynh, *ynl;
    float *xz, *xc0, *xc1, *dbc0, *dbc1, *y0, *y1;
    float *P0, *Q0, *P1, *Q1;
    int* flags;
    cudaGetSymbolAddress((void**)&lnh,  g_lnh);
    cudaGetSymbolAddress((void**)&lnl,  g_lnl);
    cudaGetSymbolAddress((void**)&wih,  g_wih);
    cudaGetSymbolAddress((void**)&wil,  g_wil);
    cudaGetSymbolAddress((void**)&woh,  g_woh);
    cudaGetSymbolAddress((void**)&wol,  g_wol);
    cudaGetSymbolAddress((void**)&ynh,  g_ynh);
    cudaGetSymbolAddress((void**)&ynl,  g_ynl);
    cudaGetSymbolAddress((void**)&xz,   g_xz);
    cudaGetSymbolAddress((void**)&xc0,  g_xc0);
    cudaGetSymbolAddress((void**)&xc1,  g_xc1);
    cudaGetSymbolAddress((void**)&dbc0, g_dbc0);
    cudaGetSymbolAddress((void**)&dbc1, g_dbc1);
    cudaGetSymbolAddress((void**)&y0,   g_y0);
    cudaGetSymbolAddress((void**)&y1,   g_y1);
    cudaGetSymbolAddress((void**)&P0,   g_P0);
    cudaGetSymbolAddress((void**)&Q0,   g_Q0);
    cudaGetSymbolAddress((void**)&P1,   g_P1);
    cudaGetSymbolAddress((void**)&Q1,   g_Q1);
    cudaGetSymbolAddress((void**)&flags, g_flags);

    cudaFuncSetAttribute(k_mma<false>, cudaFuncAttributeMaxDynamicSharedMemorySize, MMA_SMEM);
    cudaFuncSetAttribute(k_mma<true>,  cudaFuncAttributeMaxDynamicSharedMemorySize, MMA_SMEM);
    cudaFuncSetAttribute(k_scan, cudaFuncAttributeMaxDynamicSharedMemorySize, SCAN_SMEM);

    // 0. convert weights to bf16 hi/lo
    k_cvt<<<(2*DI*DM + 255)/256, 256>>>(in_proj_w,  wih, wil, 2*DI*DM);
    k_cvt<<<(DM*DI   + 255)/256, 256>>>(out_proj_w, woh, wol, DM*DI);

    // 1. LayerNorm -> bf16 hi/lo
    k_layernorm<<<NTOK / 8, 256>>>(x, ln_w, ln_b, lnh, lnl);

    // 2. in_proj (mma.sync split-bf16): (16384,512) x (1024,512)^T -> xz fp32
    k_mma<false><<<dim3(2*DI/128, NTOK/128), 256, MMA_SMEM>>>(lnh, lnl, wih, wil, xz, 2*DI, nullptr);

    // 3. conv + silu (fwd and reversed-bwd)
    k_conv<<<(NTOK * DI) / 256, 256>>>(xz, conv_w, conv_b, conv_w_b, conv_b_b, xc0, xc1);

    // 4. x_proj both branches: (16384,512) x (48,512)^T -> dbc (16384,48)
    k_gemm2<<<dim3(1, NTOK/BM, 2), 256>>>(
        xc0, xc1, DI, x_proj_w, x_proj_w_b, dbc0, dbc1, NTOK, DBCW, DI);

    // 5. fused dt_proj + selective scan (single pass, decoupled lookback)
    k_zero<<<2, 1024>>>(flags);
    k_scan<<<dim3(DI/128, BATCH, NCH*2), 128, SCAN_SMEM>>>(
        xc0, xc1, dbc0, dbc1, A_log, A_log_b,
        dt_proj_w, dt_proj_w_b, dt_proj_b, dt_proj_b_b,
        Dp, D_b, y0, y1, P0, Q0, P1, Q1, flags);

    // 6. combine + silu(z) gate + RMSNorm -> bf16 hi/lo
    k_rms<<<NTOK / 8, 256>>>(y0, y1, xz, rms_w, ynh, ynl);

    // 7. out_proj (mma.sync split-bf16) + residual -> d_out
    k_mma<true><<<dim3(DM/128, NTOK/128), 256, MMA_SMEM>>>(ynh, ynl, woh, wol, out, DM, x);
}

// round 6
// speedup vs baseline: 2.1110x; 1.0602x over previous
#include <cuda_runtime.h>
#include <cuda_bf16.h>
#include <cstdint>

// ---------------- problem constants ----------------
#define BATCH   4
#define LSEQ    4096
#define NTOK    (BATCH*LSEQ)       // 16384
#define DM      512
#define DI      512
#define DS      8
#define DTRANK  32
#define DBCW    48                 // DT_RANK + 2*D_STATE

// chunked scan config
#define NCH     64
#define TCH     (LSEQ/NCH)         // 64
#define NCHAN   (BATCH*DI)         // 2048
#define CHTOT   (NCHAN*NCH)        // 131072

// ---------------- scratch (device globals; no runtime alloc) ----------------
__device__ __nv_bfloat16 g_lnh[NTOK*DM];
__device__ __nv_bfloat16 g_lnl[NTOK*DM];
__device__ __nv_bfloat16 g_wih[2*DI*DM];
__device__ __nv_bfloat16 g_wil[2*DI*DM];
__device__ __nv_bfloat16 g_woh[DM*DI];
__device__ __nv_bfloat16 g_wol[DM*DI];
__device__ __nv_bfloat16 g_ynh[NTOK*DI];
__device__ __nv_bfloat16 g_ynl[NTOK*DI];
__device__ float g_xz  [NTOK*2*DI];
__device__ float g_dbc0[NTOK*DBCW];
__device__ float g_dbc1[NTOK*DBCW];
__device__ float g_y0  [NTOK*DI];
__device__ float g_y1  [NTOK*DI];
__device__ float g_P0  [DS*CHTOT];
__device__ float g_Q0  [DS*CHTOT];
__device__ float g_P1  [DS*CHTOT];
__device__ float g_Q1  [DS*CHTOT];
__device__ int   g_flags[2048];

// ---------------- helpers ----------------
__device__ __forceinline__ uint32_t smem_u32(const void* p) {
    uint32_t a;
    asm("{ .reg .u64 t; cvta.to.shared.u64 t, %1; cvt.u32.u64 %0, t; }" : "=r"(a) : "l"(p));
    return a;
}
__device__ __forceinline__ void ldsm4(uint32_t* r, uint32_t addr) {
    asm volatile("ldmatrix.sync.aligned.m8n8.x4.shared.b16 {%0,%1,%2,%3}, [%4];"
        : "=r"(r[0]), "=r"(r[1]), "=r"(r[2]), "=r"(r[3]) : "r"(addr));
}
__device__ __forceinline__ void mma16816(float* c, const uint32_t* a, const uint32_t* b) {
    asm volatile("mma.sync.aligned.m16n8k16.row.col.f32.bf16.bf16.f32 "
        "{%0,%1,%2,%3},{%4,%5,%6,%7},{%8,%9},{%0,%1,%2,%3};"
        : "+f"(c[0]), "+f"(c[1]), "+f"(c[2]), "+f"(c[3])
        : "r"(a[0]), "r"(a[1]), "r"(a[2]), "r"(a[3]), "r"(b[0]), "r"(b[1]));
}
__device__ __forceinline__ float silu(float v) { return v / (1.f + __expf(-v)); }

// ---------------- mma.sync split-bf16 GEMM, 512 threads, 3-stage -------------
#define KCH     64
#define NKCH    (512/KCH)          // 8
#define TILEB   16384              // one 128x64 bf16 tile in smem
#define STG_SZ  (4*TILEB)          // Ah, Al, Bh, Bl = 65536
#define MMA_SMEM (3*STG_SZ)        // 196608

__device__ __forceinline__ void mma_load_chunk(
    const __nv_bfloat16* __restrict__ Ah, const __nv_bfloat16* __restrict__ Al,
    const __nv_bfloat16* __restrict__ Bh, const __nv_bfloat16* __restrict__ Bl,
    int m0, int n0, int kc, uint32_t stage)
{
    const int t = threadIdx.x;
#pragma unroll
    for (int it = 0; it < 8; it++) {
        int idx   = it * 512 + t;
        int tile  = idx >> 10;             // 0:Ah 1:Al 2:Bh 3:Bl
        int local = idx & 1023;
        int row   = local >> 3;
        int c     = local & 7;
        const __nv_bfloat16* gb = (tile == 0) ? Ah : (tile == 1) ? Al : (tile == 2) ? Bh : Bl;
        int base = (tile < 2) ? m0 : n0;
        const void* ga = gb + (size_t)(base + row) * 512 + kc * KCH + c * 8;
        uint32_t sa = stage + tile * TILEB + row * 128 + ((c ^ (row & 7)) << 4);
        asm volatile("cp.async.cg.shared.global [%0], [%1], 16;" :: "r"(sa), "l"(ga));
    }
}

template<bool RESID>
__global__ __launch_bounds__(512)
void k_mma(const __nv_bfloat16* __restrict__ Ah, const __nv_bfloat16* __restrict__ Al,
           const __nv_bfloat16* __restrict__ Bh, const __nv_bfloat16* __restrict__ Bl,
           float* __restrict__ C, int N, const float* __restrict__ resid)
{
    extern __shared__ __align__(128) char smem[];
    const uint32_t sb = smem_u32(smem);
    const int m0 = blockIdx.y * 128;
    const int n0 = blockIdx.x * 128;
    const int w  = threadIdx.x >> 5;
    const int lane = threadIdx.x & 31;
    const int wm = (w >> 2) * 32;      // 4x4 warp grid, warp tile 32x32
    const int wn = (w & 3) * 32;

    float acc[2][4][4];
#pragma unroll
    for (int i = 0; i < 2; i++)
#pragma unroll
        for (int j = 0; j < 4; j++)
#pragma unroll
            for (int q = 0; q < 4; q++) acc[i][j][q] = 0.f;

    const int ar  = lane & 15;
    const int ach = lane >> 4;
    const int bt8 = lane & 7;
    const int bn8 = (lane >> 4) << 3;
    const int bch = (lane >> 3) & 1;

    mma_load_chunk(Ah, Al, Bh, Bl, m0, n0, 0, sb);
    asm volatile("cp.async.commit_group;");
    mma_load_chunk(Ah, Al, Bh, Bl, m0, n0, 1, sb + STG_SZ);
    asm volatile("cp.async.commit_group;");

    for (int i = 0; i < NKCH; i++) {
        if (i < NKCH - 1) asm volatile("cp.async.wait_group 1;");
        else              asm volatile("cp.async.wait_group 0;");
        __syncthreads();

        if (i < NKCH - 2) {
            mma_load_chunk(Ah, Al, Bh, Bl, m0, n0, i + 2, sb + ((i + 2) % 3) * STG_SZ);
            asm volatile("cp.async.commit_group;");
        }

        const uint32_t stg = sb + (i % 3) * STG_SZ;
        const uint32_t sAh = stg, sAl = stg + TILEB, sBh = stg + 2*TILEB, sBl = stg + 3*TILEB;

#pragma unroll
        for (int ks = 0; ks < 4; ks++) {
            uint32_t ah[2][4], al[2][4], bh[2][4], bl[2][4];
#pragma unroll
            for (int mi = 0; mi < 2; mi++) {
                int r = wm + mi * 16 + ar;
                int c = ks * 2 + ach;
                uint32_t off = r * 128 + (((uint32_t)(c ^ (r & 7))) << 4);
                ldsm4(ah[mi], sAh + off);
                ldsm4(al[mi], sAl + off);
            }
#pragma unroll
            for (int ni = 0; ni < 2; ni++) {
                int n = wn + ni * 16 + bn8 + bt8;
                int c = ks * 2 + bch;
                uint32_t off = n * 128 + (((uint32_t)(c ^ (n & 7))) << 4);
                ldsm4(bh[ni], sBh + off);
                ldsm4(bl[ni], sBl + off);
            }
#pragma unroll
            for (int mi = 0; mi < 2; mi++)
#pragma unroll
                for (int nj = 0; nj < 4; nj++) {
                    const uint32_t* bhp = &bh[nj >> 1][(nj & 1) * 2];
                    const uint32_t* blp = &bl[nj >> 1][(nj & 1) * 2];
                    mma16816(acc[mi][nj], ah[mi], bhp);
                    mma16816(acc[mi][nj], ah[mi], blp);
                    mma16816(acc[mi][nj], al[mi], bhp);
                }
        }
    }

#pragma unroll
    for (int mi = 0; mi < 2; mi++) {
        int m = m0 + wm + mi * 16 + (lane >> 2);
#pragma unroll
        for (int nj = 0; nj < 4; nj++) {
            int n = n0 + wn + nj * 8 + ((lane & 3) << 1);
            float2 v0 = make_float2(acc[mi][nj][0], acc[mi][nj][1]);
            float2 v1 = make_float2(acc[mi][nj][2], acc[mi][nj][3]);
            if (RESID) {
                float2 r0 = *(const float2*)(resid + (size_t)m * N + n);
                float2 r1 = *(const float2*)(resid + (size_t)(m + 8) * N + n);
                v0.x += r0.x; v0.y += r0.y; v1.x += r1.x; v1.y += r1.y;
            }
            *(float2*)(C + (size_t)m * N + n)       = v0;
            *(float2*)(C + (size_t)(m + 8) * N + n) = v1;
        }
    }
}

// ---------------- fp32 -> bf16 hi/lo weight convert ----------------
__global__ void k_cvt(const float* __restrict__ w, __nv_bfloat16* __restrict__ hi,
                      __nv_bfloat16* __restrict__ lo, int n)
{
    int i = blockIdx.x * blockDim.x + threadIdx.x;
    if (i < n) {
        float v = w[i];
        __nv_bfloat16 h = __float2bfloat16(v);
        hi[i] = h;
        lo[i] = __float2bfloat16(v - __bfloat162float(h));
    }
}

// ---------------- LayerNorm -> bf16 hi/lo ----------------
__global__ void k_layernorm(const float* __restrict__ x,
                            const float* __restrict__ w,
                            const float* __restrict__ b,
                            __nv_bfloat16* __restrict__ oh,
                            __nv_bfloat16* __restrict__ ol)
{
    int tok  = blockIdx.x * 8 + (threadIdx.x >> 5);
    int lane = threadIdx.x & 31;
    const float* row = x + (size_t)tok * DM;

    float4 v[4];
    float s = 0.f, s2 = 0.f;
#pragma unroll
    for (int i = 0; i < 4; i++) {
        v[i] = *(const float4*)(row + i * 128 + lane * 4);
        s  += v[i].x + v[i].y + v[i].z + v[i].w;
        s2 += v[i].x*v[i].x + v[i].y*v[i].y + v[i].z*v[i].z + v[i].w*v[i].w;
    }
#pragma unroll
    for (int o = 16; o; o >>= 1) {
        s  += __shfl_xor_sync(0xffffffffu, s,  o);
        s2 += __shfl_xor_sync(0xffffffffu, s2, o);
    }
    float mu   = s * (1.f / DM);
    float var  = s2 * (1.f / DM) - mu * mu;
    float rinv = rsqrtf(var + 1e-5f);

#pragma unroll
    for (int i = 0; i < 4; i++) {
        int d = i * 128 + lane * 4;
        float4 w4 = *(const float4*)(w + d);
        float4 b4 = *(const float4*)(b + d);
        float o4[4];
        o4[0] = (v[i].x - mu) * rinv * w4.x + b4.x;
        o4[1] = (v[i].y - mu) * rinv * w4.y + b4.y;
        o4[2] = (v[i].z - mu) * rinv * w4.z + b4.z;
        o4[3] = (v[i].w - mu) * rinv * w4.w + b4.w;
        __nv_bfloat16 hh[4], ll[4];
#pragma unroll
        for (int q = 0; q < 4; q++) {
            hh[q] = __float2bfloat16(o4[q]);
            ll[q] = __float2bfloat16(o4[q] - __bfloat162float(hh[q]));
        }
        *(uint2*)(oh + (size_t)tok * DM + d) = *(uint2*)hh;
        *(uint2*)(ol + (size_t)tok * DM + d) = *(uint2*)ll;
    }
}

// ---------------- x_proj SGEMM with fused conv+silu A ------------------------
// A[tok][d] = silu(conv(xz_x)) computed on the fly. Both branches via z-dim.
#define BM 64
#define BN 64
#define BKK 16

__global__ __launch_bounds__(256)
void k_gemm2(const float* __restrict__ xz,
             const float* __restrict__ cw0, const float* __restrict__ cb0,
             const float* __restrict__ cw1, const float* __restrict__ cb1,
             const float* __restrict__ W0,  const float* __restrict__ W1,
             float* __restrict__ C0, float* __restrict__ C1)
{
    const int br = blockIdx.z;
    const float* W  = br ? W1  : W0;
    const float* cw = br ? cw1 : cw0;
    const float* cb = br ? cb1 : cb0;
    float* C = br ? C1 : C0;
    const int N = DBCW, K = DI;

    __shared__ __align__(16) float As[BKK][BM + 4];
    __shared__ __align__(16) float Ws[BKK][BN + 4];

    const int bm = blockIdx.y * BM;
    const int bn = blockIdx.x * BN;
    const int tid = threadIdx.x;
    const int tx = tid & 15;
    const int ty = tid >> 4;
    const int lr = tid >> 2;
    const int lq = tid & 3;

    float acc[4][4];
#pragma unroll
    for (int i = 0; i < 4; i++)
#pragma unroll
        for (int j = 0; j < 4; j++) acc[i][j] = 0.f;

    // token mapping for this thread's A row
    const int tok = bm + lr;            // scan-space token
    const int s   = tok & (LSEQ - 1);
    const int bb  = tok >> 12;
    const int row = br ? (bb * LSEQ + LSEQ - 1 - s) : tok;
    const int prow = br ? row + 1 : row - 1;
    const bool pv = s > 0;

    const bool wok = (bn + lr) < N;
    const float* Wp = W + (size_t)(wok ? (bn + lr) : 0) * K + lq * 4;

    for (int k0 = 0; k0 < K; k0 += BKK) {
        const int d = k0 + lq * 4;
        float4 xcur = *(const float4*)(xz + (size_t)row * (2 * DI) + d);
        float4 xprv = pv ? *(const float4*)(xz + (size_t)prow * (2 * DI) + d)
                         : make_float4(0.f, 0.f, 0.f, 0.f);
        float4 cwa = *(const float4*)(cw + d * 2);       // w0[d],w1[d],w0[d+1],w1[d+1]
        float4 cwbv = *(const float4*)(cw + d * 2 + 4);  // d+2, d+3
        float4 cbv = *(const float4*)(cb + d);
        float4 av;
        av.x = silu(fmaf(cwa.x,  xprv.x, fmaf(cwa.y,  xcur.x, cbv.x)));
        av.y = silu(fmaf(cwa.z,  xprv.y, fmaf(cwa.w,  xcur.y, cbv.y)));
        av.z = silu(fmaf(cwbv.x, xprv.z, fmaf(cwbv.y, xcur.z, cbv.z)));
        av.w = silu(fmaf(cwbv.z, xprv.w, fmaf(cwbv.w, xcur.w, cbv.w)));

        float4 wv = wok ? *(const float4*)(Wp + k0) : make_float4(0.f, 0.f, 0.f, 0.f);
        __syncthreads();
        As[lq*4+0][lr] = av.x; As[lq*4+1][lr] = av.y;
        As[lq*4+2][lr] = av.z; As[lq*4+3][lr] = av.w;
        Ws[lq*4+0][lr] = wv.x; Ws[lq*4+1][lr] = wv.y;
        Ws[lq*4+2][lr] = wv.z; Ws[lq*4+3][lr] = wv.w;
        __syncthreads();
#pragma unroll
        for (int kk = 0; kk < BKK; kk++) {
            float4 ra = *(const float4*)(&As[kk][ty * 4]);
            float4 rw = *(const float4*)(&Ws[kk][tx * 4]);
            float a4[4] = { ra.x, ra.y, ra.z, ra.w };
            float w4[4] = { rw.x, rw.y, rw.z, rw.w };
#pragma unroll
            for (int i = 0; i < 4; i++)
#pragma unroll
                for (int j = 0; j < 4; j++)
                    acc[i][j] = fmaf(a4[i], w4[j], acc[i][j]);
        }
    }

#pragma unroll
    for (int i = 0; i < 4; i++) {
        int m = bm + ty * 4 + i;
#pragma unroll
        for (int j = 0; j < 4; j++) {
            int n = bn + tx * 4 + j;
            if (n < N) C[(size_t)m * N + n] = acc[i][j];
        }
    }
}

// ---------------- zero lookback flags ----------------
__global__ void k_zero(int* __restrict__ flags) {
    flags[blockIdx.x * 1024 + threadIdx.x] = 0;
}

// ---------------- fused conv + dt_proj + softplus + lookback scan -----------
#define SCAN_SMEM (TCH*128*4 + TCH*49*4)   // 32768 + 12544 = 45312

__global__ __launch_bounds__(128)
void k_scan(const float* __restrict__ xz,
            const float* __restrict__ dbc0, const float* __restrict__ dbc1,
            const float* __restrict__ cw0,  const float* __restrict__ cb0,
            const float* __restrict__ cw1,  const float* __restrict__ cb1,
            const float* __restrict__ Alog0, const float* __restrict__ Alog1,
            const float* __restrict__ dtw0, const float* __restrict__ dtw1,
            const float* __restrict__ dtb0, const float* __restrict__ dtb1,
            const float* __restrict__ Dp0,  const float* __restrict__ Dp1,
            float* __restrict__ y0g, float* __restrict__ y1g,
            float* __restrict__ P0g, float* __restrict__ Q0g,
            float* __restrict__ P1g, float* __restrict__ Q1g,
            int* __restrict__ flags)
{
    extern __shared__ float sm[];
    float* delta_s = sm;                 // [TCH][128]
    float* dbc_s   = sm + TCH * 128;     // [TCH][49]

    const int t  = threadIdx.x;
    const int dg = blockIdx.x;
    const int b  = blockIdx.y;
    const int br = blockIdx.z & 1;
    const int chunk = blockIdx.z >> 1;
    const int d  = dg * 128 + t;

    const float* dbc = br ? dbc1 : dbc0;
    const float* Alg = br ? Alog1 : Alog0;
    const float* Wdt = br ? dtw1 : dtw0;
    const float* Bdt = br ? dtb1 : dtb0;
    const float* Dpp = br ? Dp1  : Dp0;
    const float* cwp = br ? cw1 : cw0;
    const float* cbp = br ? cb1 : cb0;
    float* y  = br ? y1g : y0g;
    float* Pg = br ? P1g : P0g;
    float* Qg = br ? Q1g : Q0g;

    // stage Wdt rows into smem (aliases delta region), then regs
    for (int i = t; i < 128 * 32; i += 128) {
        int rw_ = i >> 5, k = i & 31;
        sm[rw_ * 33 + k] = Wdt[(size_t)(dg * 128) * 32 + i];
    }
    const int tok0 = b * LSEQ + chunk * TCH;
    for (int i = t; i < TCH * 48; i += 128)
        dbc_s[(i / 48) * 49 + (i % 48)] = dbc[(size_t)tok0 * 48 + i];
    __syncthreads();
    float w[32];
#pragma unroll
    for (int k = 0; k < 32; k++) w[k] = sm[t * 33 + k];
    __syncthreads();

    float Av[DS];
    {
        float4 a0 = *(const float4*)(Alg + d * DS);
        float4 a1 = *(const float4*)(Alg + d * DS + 4);
        Av[0] = -__expf(a0.x); Av[1] = -__expf(a0.y); Av[2] = -__expf(a0.z); Av[3] = -__expf(a0.w);
        Av[4] = -__expf(a1.x); Av[5] = -__expf(a1.y); Av[6] = -__expf(a1.z); Av[7] = -__expf(a1.w);
    }
    const float Av0 = Av[0];
    bool uni = true;
#pragma unroll
    for (int n = 1; n < DS; n++)
        uni = uni && (fabsf(Av[n] - (n + 1) * Av0) <= 2e-5f * (n + 1));

    const float bias = Bdt[d];
    const float Dd   = Dpp[d];
    const float cwd0 = cwp[d * 2], cwd1 = cwp[d * 2 + 1], cbd = cbp[d];

    // conv input walk: xz row r0 + dir*tt, prev = row - dir (rolling register)
    const int s0  = chunk * TCH;
    const int r0  = br ? (b * LSEQ + LSEQ - 1 - s0) : tok0;
    const int dir = br ? -1 : 1;

    // sweep 1: conv+silu -> u, dt dot -> delta (cached), local (P, Q)
    float h[DS], P[DS], S = 0.f;
#pragma unroll
    for (int n = 0; n < DS; n++) { h[n] = 0.f; P[n] = 1.f; }

    float xprev = (s0 > 0) ? xz[(size_t)(r0 - dir) * (2 * DI) + d] : 0.f;
    for (int tt = 0; tt < TCH; tt++) {
        float xcur = xz[(size_t)(r0 + dir * tt) * (2 * DI) + d];
        float u = silu(fmaf(cwd0, xprev, fmaf(cwd1, xcur, cbd)));
        xprev = xcur;

        const float* row = &dbc_s[tt * 49];
        float a0 = bias, a1 = 0.f, a2 = 0.f, a3 = 0.f;
#pragma unroll
        for (int k = 0; k < 32; k += 4) {
            a0 = fmaf(row[k + 0], w[k + 0], a0);
            a1 = fmaf(row[k + 1], w[k + 1], a1);
            a2 = fmaf(row[k + 2], w[k + 2], a2);
            a3 = fmaf(row[k + 3], w[k + 3], a3);
        }
        float v = (a0 + a1) + (a2 + a3);
        float dl = (v > 20.f) ? v : log1pf(__expf(v));
        delta_s[tt * 128 + t] = dl;
        float du = dl * u;
        if (uni) {
            S += dl;
            float e1 = __expf(dl * Av0);
            float an = 1.f;
#pragma unroll
            for (int n = 0; n < DS; n++) {
                an *= e1;
                h[n] = fmaf(an, h[n], du * row[32 + n]);
            }
        } else {
#pragma unroll
            for (int n = 0; n < DS; n++) {
                float a = __expf(dl * Av[n]);
                P[n] *= a;
                h[n] = fmaf(a, h[n], du * row[32 + n]);
            }
        }
    }
    if (uni) {
#pragma unroll
        for (int n = 0; n < DS; n++) P[n] = __expf(S * Av[n]);
    }

    // publish local (P, Q) then release flag
    const int cidx = chunk * NCHAN + b * DI + d;
#pragma unroll
    for (int n = 0; n < DS; n++) {
        Pg[n * CHTOT + cidx] = P[n];
        Qg[n * CHTOT + cidx] = h[n];
    }
    __threadfence();
    __syncthreads();
    if (t == 0) {
        int fi = blockIdx.z * 16 + b * 4 + dg;
        asm volatile("st.global.release.gpu.b32 [%0], %1;" :: "l"(flags + fi), "r"(1) : "memory");
    }

    // lookback
    float h0[DS], pref[DS];
#pragma unroll
    for (int n = 0; n < DS; n++) { h0[n] = 0.f; pref[n] = 1.f; }
    for (int j = chunk - 1; j >= 0; j--) {
        const int fj = (j * 2 + br) * 16 + b * 4 + dg;
        int f;
        do {
            asm volatile("ld.global.acquire.gpu.b32 %0, [%1];" : "=r"(f) : "l"(flags + fj) : "memory");
            if (!f) __nanosleep(64);
        } while (!f);
        const int idxj = j * NCHAN + b * DI + d;
#pragma unroll
        for (int n = 0; n < DS; n++) {
            h0[n] = fmaf(pref[n], Qg[n * CHTOT + idxj], h0[n]);
            pref[n] *= Pg[n * CHTOT + idxj];
        }
    }

    // sweep 2: full recurrence from h0, emit y (u recomputed; xz L2-hot)
#pragma unroll
    for (int n = 0; n < DS; n++) h[n] = h0[n];
    xprev = (s0 > 0) ? xz[(size_t)(r0 - dir) * (2 * DI) + d] : 0.f;
    for (int tt = 0; tt < TCH; tt++) {
        float xcur = xz[(size_t)(r0 + dir * tt) * (2 * DI) + d];
        float u = silu(fmaf(cwd0, xprev, fmaf(cwd1, xcur, cbd)));
        xprev = xcur;

        float dl = delta_s[tt * 128 + t];
        float du = dl * u;
        const float* row = &dbc_s[tt * 49];
        float yv = 0.f;
        if (uni) {
            float e1 = __expf(dl * Av0);
            float an = 1.f;
#pragma unroll
            for (int n = 0; n < DS; n++) {
                an *= e1;
                h[n] = fmaf(an, h[n], du * row[32 + n]);
                yv = fmaf(h[n], row[40 + n], yv);
            }
        } else {
#pragma unroll
            for (int n = 0; n < DS; n++) {
                float a = __expf(dl * Av[n]);
                h[n] = fmaf(a, h[n], du * row[32 + n]);
                yv = fmaf(h[n], row[40 + n], yv);
            }
        }
        y[(size_t)(tok0 + tt) * DI + d] = fmaf(u, Dd, yv);
    }
}

// ---------------- combine branches, gate, RMSNorm -> bf16 hi/lo ---------------
__global__ void k_rms(const float* __restrict__ yf, const float* __restrict__ yb,
                      const float* __restrict__ xz, const float* __restrict__ rw,
                      __nv_bfloat16* __restrict__ oh, __nv_bfloat16* __restrict__ ol)
{
    int tok  = blockIdx.x * 8 + (threadIdx.x >> 5);
    int lane = threadIdx.x & 31;
    int s    = tok & (LSEQ - 1);
    int rtok = tok - s + (LSEQ - 1 - s);

    float4 v[4];
    float ss = 0.f;
#pragma unroll
    for (int i = 0; i < 4; i++) {
        int d = i * 128 + lane * 4;
        float4 a = *(const float4*)(yf + (size_t)tok * DI + d);
        float4 c = *(const float4*)(yb + (size_t)rtok * DI + d);
        float4 z = *(const float4*)(xz + (size_t)tok * (2 * DI) + DI + d);
        float4 o;
        o.x = 0.5f * (a.x + c.x) * silu(z.x);
        o.y = 0.5f * (a.y + c.y) * silu(z.y);
        o.z = 0.5f * (a.z + c.z) * silu(z.z);
        o.w = 0.5f * (a.w + c.w) * silu(z.w);
        ss += o.x*o.x + o.y*o.y + o.z*o.z + o.w*o.w;
        v[i] = o;
    }
#pragma unroll
    for (int o = 16; o; o >>= 1) ss += __shfl_xor_sync(0xffffffffu, ss, o);
    float sc = rsqrtf(ss * (1.f / DI) + 1e-5f);

#pragma unroll
    for (int i = 0; i < 4; i++) {
        int d = i * 128 + lane * 4;
        float4 w4 = *(const float4*)(rw + d);
        float o4[4];
        o4[0] = v[i].x * sc * w4.x;
        o4[1] = v[i].y * sc * w4.y;
        o4[2] = v[i].z * sc * w4.z;
        o4[3] = v[i].w * sc * w4.w;
        __nv_bfloat16 hh[4], ll[4];
#pragma unroll
        for (int q = 0; q < 4; q++) {
            hh[q] = __float2bfloat16(o4[q]);
            ll[q] = __float2bfloat16(o4[q] - __bfloat162float(hh[q]));
        }
        *(uint2*)(oh + (size_t)tok * DI + d) = *(uint2*)hh;
        *(uint2*)(ol + (size_t)tok * DI + d) = *(uint2*)ll;
    }
}

// ---------------- host launch ----------------
extern "C" void kernel_launch(void* const* d_in, const int* in_sizes, int n_in,
                              void* d_out, int out_size)
{
    const float* x          = (const float*)d_in[0];
    const float* ln_w       = (const float*)d_in[1];
    const float* ln_b       = (const float*)d_in[2];
    const float* in_proj_w  = (const float*)d_in[3];
    const float* conv_w     = (const float*)d_in[4];
    const float* conv_b     = (const float*)d_in[5];
    const float* x_proj_w   = (const float*)d_in[6];
    const float* dt_proj_w  = (const float*)d_in[7];
    const float* dt_proj_b  = (const float*)d_in[8];
    const float* A_log      = (const float*)d_in[9];
    const float* Dp         = (const float*)d_in[10];
    const float* conv_w_b   = (const float*)d_in[11];
    const float* conv_b_b   = (const float*)d_in[12];
    const float* x_proj_w_b = (const float*)d_in[13];
    const float* dt_proj_w_b= (const float*)d_in[14];
    const float* dt_proj_b_b= (const float*)d_in[15];
    const float* A_log_b    = (const float*)d_in[16];
    const float* D_b        = (const float*)d_in[17];
    const float* rms_w      = (const float*)d_in[18];
    const float* out_proj_w = (const float*)d_in[19];
    float* out = (float*)d_out;

    __nv_bfloat16 *lnh, *lnl, *wih, *wil, *woh, *wol, *ynh, *ynl;
    float *xz, *dbc0, *dbc1, *y0, *y1;
    float *P0, *Q0, *P1, *Q1;
    int* flags;
    cudaGetSymbolAddress((void**)&lnh,  g_lnh);
    cudaGetSymbolAddress((void**)&lnl,  g_lnl);
    cudaGetSymbolAddress((void**)&wih,  g_wih);
    cudaGetSymbolAddress((void**)&wil,  g_wil);
    cudaGetSymbolAddress((void**)&woh,  g_woh);
    cudaGetSymbolAddress((void**)&wol,  g_wol);
    cudaGetSymbolAddress((void**)&ynh,  g_ynh);
    cudaGetSymbolAddress((void**)&ynl,  g_ynl);
    cudaGetSymbolAddress((void**)&xz,   g_xz);
    cudaGetSymbolAddress((void**)&dbc0, g_dbc0);
    cudaGetSymbolAddress((void**)&dbc1, g_dbc1);
    cudaGetSymbolAddress((void**)&y0,   g_y0);
    cudaGetSymbolAddress((void**)&y1,   g_y1);
    cudaGetSymbolAddress((void**)&P0,   g_P0);
    cudaGetSymbolAddress((void**)&Q0,   g_Q0);
    cudaGetSymbolAddress((void**)&P1,   g_P1);
    cudaGetSymbolAddress((void**)&Q1,   g_Q1);
    cudaGetSymbolAddress((void**)&flags, g_flags);

    cudaFuncSetAttribute(k_mma<false>, cudaFuncAttributeMaxDynamicSharedMemorySize, MMA_SMEM);
    cudaFuncSetAttribute(k_mma<true>,  cudaFuncAttributeMaxDynamicSharedMemorySize, MMA_SMEM);
    cudaFuncSetAttribute(k_scan, cudaFuncAttributeMaxDynamicSharedMemorySize, SCAN_SMEM);

    // 0. convert weights to bf16 hi/lo
    k_cvt<<<(2*DI*DM + 255)/256, 256>>>(in_proj_w,  wih, wil, 2*DI*DM);
    k_cvt<<<(DM*DI   + 255)/256, 256>>>(out_proj_w, woh, wol, DM*DI);

    // 1. LayerNorm -> bf16 hi/lo
    k_layernorm<<<NTOK / 8, 256>>>(x, ln_w, ln_b, lnh, lnl);

    // 2. in_proj (mma.sync split-bf16): (16384,512) x (1024,512)^T -> xz fp32
    k_mma<false><<<dim3(2*DI/128, NTOK/128), 512, MMA_SMEM>>>(lnh, lnl, wih, wil, xz, 2*DI, nullptr);

    // 3. x_proj with fused conv+silu, both branches
    k_gemm2<<<dim3(1, NTOK/BM, 2), 256>>>(
        xz, conv_w, conv_b, conv_w_b, conv_b_b,
        x_proj_w, x_proj_w_b, dbc0, dbc1);

    // 4. fused conv + dt_proj + selective scan (single pass, decoupled lookback)
    k_zero<<<2, 1024>>>(flags);
    k_scan<<<dim3(DI/128, BATCH, NCH*2), 128, SCAN_SMEM>>>(
        xz, dbc0, dbc1, conv_w, conv_b, conv_w_b, conv_b_b,
        A_log, A_log_b, dt_proj_w, dt_proj_w_b, dt_proj_b, dt_proj_b_b,
        Dp, D_b, y0, y1, P0, Q0, P1, Q1, flags);

    // 5. combine + silu(z) gate + RMSNorm -> bf16 hi/lo
    k_rms<<<NTOK / 8, 256>>>(y0, y1, xz, rms_w, ynh, ynl);

    // 6. out_proj (mma.sync split-bf16) + residual -> d_out
    k_mma<true><<<dim3(DM/128, NTOK/128), 512, MMA_SMEM>>>(ynh, ynl, woh, wol, out, DM, x);
}